// round 7
// baseline (speedup 1.0000x reference)
#include <cuda_runtime.h>
#include <cuda_fp16.h>
#include <math.h>
#include <stdint.h>

#define BATCH   2
#define SEQ     1024
#define NROWS   (BATCH * SEQ)
#define DMODEL  1024
#define NHEAD   16
#define HDIM    64
#define TDIM    1024
#define FFDIM   4096
#define NLAYER  8
#define VOCAB   32000

#define WU16  0
#define WO16  25165824u
#define F116  33554432u
#define F216  67108864u
#define EMB16 100663296u
#define W16_TOTAL 133431296u

__device__ float  g_x [NROWS * DMODEL];
__device__ float  g_u [NROWS * 3 * TDIM];
__device__ __half g_xn16[NROWS * DMODEL];
__device__ __half g_at16[NROWS * TDIM];
__device__ __half g_h16 [NROWS * FFDIM];
__device__ __half g_w16 [W16_TOTAL];

__device__ __forceinline__ float gelu_exact(float v) {
    return 0.5f * v * (1.0f + erff(v * 0.70710678118654752440f));
}
__device__ __forceinline__ uint32_t s2u(const void* p) {
    uint32_t a;
    asm("{ .reg .u64 t; cvta.to.shared.u64 t, %1; cvt.u32.u64 %0, t; }" : "=r"(a) : "l"(p));
    return a;
}
__device__ __forceinline__ void cp16(uint32_t s, const void* g) {
    asm volatile("cp.async.cg.shared.global [%0], [%1], 16;" :: "r"(s), "l"(g));
}
__device__ __forceinline__ void ldsm4(unsigned* r, uint32_t a) {
    asm volatile("ldmatrix.sync.aligned.m8n8.x4.shared.b16 {%0,%1,%2,%3}, [%4];"
        : "=r"(r[0]), "=r"(r[1]), "=r"(r[2]), "=r"(r[3]) : "r"(a));
}
__device__ __forceinline__ void mma_f16(float* c, const unsigned* a, const unsigned* b) {
    asm volatile(
        "mma.sync.aligned.m16n8k16.row.col.f32.f16.f16.f32 "
        "{%0,%1,%2,%3},{%4,%5,%6,%7},{%8,%9},{%0,%1,%2,%3};"
        : "+f"(c[0]), "+f"(c[1]), "+f"(c[2]), "+f"(c[3])
        : "r"(a[0]), "r"(a[1]), "r"(a[2]), "r"(a[3]), "r"(b[0]), "r"(b[1]));
}

// ---------------------------------------------------------------------------
// fp16 GEMM: C[M,N] = A[M,K] @ B[N,K]^T (+ epilogue)
// MODE 0: fp32 C      MODE 1: gelu(acc+bias) -> fp16
// MODE 2: acc(+bias)+resid -> fp32 C      MODE 3: rope(acc) -> fp32 C (QKV)
// BM=BN=128, BK=64, 3-stage cp.async pipeline (1 sync / k64), ldmatrix feeds.
// smem row stride 144B (128B data + 16 pad) -> conflict-free LDSM.
// ---------------------------------------------------------------------------
template<int MODE>
__global__ __launch_bounds__(256)
void gemm_f16(const __half* __restrict__ A, const __half* __restrict__ B,
              const float* __restrict__ bias, const float* __restrict__ resid,
              float* __restrict__ C, __half* __restrict__ C16, int N, int K)
{
    extern __shared__ __align__(128) char smem[];
    const uint32_t sb = s2u(smem);
    const int tid = threadIdx.x, warp = tid >> 5, lane = tid & 31;
    const int bm = blockIdx.y * 128, bn = blockIdx.x * 128;
    const int moff = (warp & 3) * 32, noff = (warp >> 2) * 64;
    const int g = lane >> 2, t = lane & 3;
    const int nk = K >> 6;
    const int lrow = tid >> 1, lhalf = tid & 1;

    float acc[2][8][4];
#pragma unroll
    for (int mi = 0; mi < 2; mi++)
#pragma unroll
        for (int ni = 0; ni < 8; ni++)
#pragma unroll
            for (int e = 0; e < 4; e++) acc[mi][ni][e] = 0.0f;

#define LOADST(st, ks) do { \
    const uint32_t so = sb + (uint32_t)(st) * 36864u; \
    const __half* gA = A + (size_t)(bm + lrow) * K + (ks) * 64 + lhalf * 32; \
    const __half* gB = B + (size_t)(bn + lrow) * K + (ks) * 64 + lhalf * 32; \
    const uint32_t sA = so + lrow * 144 + lhalf * 64; \
    const uint32_t sB = sA + 18432u; \
    cp16(sA, gA); cp16(sA + 16, gA + 8); cp16(sA + 32, gA + 16); cp16(sA + 48, gA + 24); \
    cp16(sB, gB); cp16(sB + 16, gB + 8); cp16(sB + 32, gB + 16); cp16(sB + 48, gB + 24); \
} while (0)

    LOADST(0, 0);
    asm volatile("cp.async.commit_group;" ::: "memory");
    if (nk > 1) LOADST(1, 1);
    asm volatile("cp.async.commit_group;" ::: "memory");

    const uint32_t aoff = (uint32_t)((moff + (lane & 15)) * 144 + ((lane >> 4) & 1) * 16);
    const uint32_t boff = 18432u +
        (uint32_t)((noff + (lane & 7) + ((lane >> 4) & 1) * 8) * 144 + ((lane >> 3) & 1) * 16);

    for (int ks = 0; ks < nk; ks++) {
        asm volatile("cp.async.wait_group %0;" :: "n"(1) : "memory");
        __syncthreads();
        if (ks + 2 < nk) { LOADST((ks + 2) % 3, ks + 2); }
        asm volatile("cp.async.commit_group;" ::: "memory");

        const uint32_t so = sb + (uint32_t)(ks % 3) * 36864u;
#pragma unroll
        for (int kk = 0; kk < 4; kk++) {
            unsigned a0[4], a1[4], b[4][4];
            ldsm4(a0, so + aoff + kk * 32);
            ldsm4(a1, so + aoff + 16 * 144 + kk * 32);
#pragma unroll
            for (int nj = 0; nj < 4; nj++)
                ldsm4(b[nj], so + boff + nj * 16 * 144 + kk * 32);
#pragma unroll
            for (int nj = 0; nj < 4; nj++) {
                mma_f16(acc[0][2 * nj],     a0, &b[nj][0]);
                mma_f16(acc[0][2 * nj + 1], a0, &b[nj][2]);
                mma_f16(acc[1][2 * nj],     a1, &b[nj][0]);
                mma_f16(acc[1][2 * nj + 1], a1, &b[nj][2]);
            }
        }
    }
#undef LOADST

    if (MODE == 3) {
        // fused RoPE: cols of this warp span one region (q/k/v); heads 64-wide
        const int region = (bn + noff) >> 10;
        if (region < 2) {
#pragma unroll
            for (int mi = 0; mi < 2; mi++) {
                const int r0 = bm + moff + 16 * mi + g;
                const float s0 = (float)(r0 & (SEQ - 1));
#pragma unroll
                for (int ni = 0; ni < 4; ni++) {
#pragma unroll
                    for (int e = 0; e < 4; e++) {
                        const int i = 8 * ni + 2 * t + (e & 1);
                        const float srow = s0 + ((e >= 2) ? 8.0f : 0.0f);
                        const float inv = exp2f(-(float)(2 * i) * (1.0f / 64.0f)
                                                * 13.287712379549449f);
                        float sn, cs;
                        sincosf(srow * inv, &sn, &cs);
                        const float v0 = acc[mi][ni][e], v1 = acc[mi][ni + 4][e];
                        acc[mi][ni][e]     = v0 * cs - v1 * sn;
                        acc[mi][ni + 4][e] = v1 * cs + v0 * sn;
                    }
                }
            }
        }
    }

#pragma unroll
    for (int mi = 0; mi < 2; mi++) {
        const int r0 = bm + moff + 16 * mi + g;
#pragma unroll
        for (int ni = 0; ni < 8; ni++) {
            const int c = bn + noff + 8 * ni + 2 * t;
            float v00 = acc[mi][ni][0], v01 = acc[mi][ni][1];
            float v10 = acc[mi][ni][2], v11 = acc[mi][ni][3];
            if (MODE == 1) {
                const float b0 = bias[c], b1 = bias[c + 1];
                v00 = gelu_exact(v00 + b0); v01 = gelu_exact(v01 + b1);
                v10 = gelu_exact(v10 + b0); v11 = gelu_exact(v11 + b1);
                *(__half2*)(C16 + (size_t)r0 * N + c)       = __floats2half2_rn(v00, v01);
                *(__half2*)(C16 + (size_t)(r0 + 8) * N + c) = __floats2half2_rn(v10, v11);
            } else {
                if (MODE == 2) {
                    if (bias) {
                        const float b0 = bias[c], b1 = bias[c + 1];
                        v00 += b0; v01 += b1; v10 += b0; v11 += b1;
                    }
                    const float2 rr0 = *(const float2*)(resid + (size_t)r0 * N + c);
                    const float2 rr1 = *(const float2*)(resid + (size_t)(r0 + 8) * N + c);
                    v00 += rr0.x; v01 += rr0.y; v10 += rr1.x; v11 += rr1.y;
                }
                float2 o0; o0.x = v00; o0.y = v01;
                float2 o1; o1.x = v10; o1.y = v11;
                *(float2*)(C + (size_t)r0 * N + c) = o0;
                *(float2*)(C + (size_t)(r0 + 8) * N + c) = o1;
            }
        }
    }
}
#define GEMM_SMEM 110592

__global__ void conv16(const float* __restrict__ s, __half* __restrict__ d, int n4)
{
    for (int i = blockIdx.x * blockDim.x + threadIdx.x; i < n4; i += gridDim.x * blockDim.x) {
        const float4 v = ((const float4*)s)[i];
        ((__half2*)d)[2 * i]     = __floats2half2_rn(v.x, v.y);
        ((__half2*)d)[2 * i + 1] = __floats2half2_rn(v.z, v.w);
    }
}

__global__ void embed_kernel(const int* __restrict__ ids,
                             const float* __restrict__ emb, float* __restrict__ x)
{
    ((float4*)(x + (size_t)blockIdx.x * DMODEL))[threadIdx.x] =
        ((const float4*)(emb + (size_t)ids[blockIdx.x] * DMODEL))[threadIdx.x];
}

// warp-per-row LayerNorm -> fp16
__global__ __launch_bounds__(256)
void layernorm_kernel(const float* __restrict__ x, const float* __restrict__ w,
                      const float* __restrict__ b, __half* __restrict__ y16)
{
    const int warp = threadIdx.x >> 5, lane = threadIdx.x & 31;
    const int row = blockIdx.x * 8 + warp;
    const float4* xr = (const float4*)(x + (size_t)row * DMODEL);

    float4 v[8];
    float s = 0.0f;
#pragma unroll
    for (int j = 0; j < 8; j++) {
        v[j] = xr[lane + 32 * j];
        s += v[j].x + v[j].y + v[j].z + v[j].w;
    }
#pragma unroll
    for (int o = 16; o > 0; o >>= 1) s += __shfl_xor_sync(0xffffffff, s, o);
    const float mu = s * (1.0f / DMODEL);

    float q = 0.0f;
#pragma unroll
    for (int j = 0; j < 8; j++) {
        const float a = v[j].x - mu, b2 = v[j].y - mu, c = v[j].z - mu, d = v[j].w - mu;
        q += a * a + b2 * b2 + c * c + d * d;
    }
#pragma unroll
    for (int o = 16; o > 0; o >>= 1) q += __shfl_xor_sync(0xffffffff, q, o);
    const float rs = rsqrtf(q * (1.0f / DMODEL) + 1e-5f);

    uint2* yr = (uint2*)(y16 + (size_t)row * DMODEL);
#pragma unroll
    for (int j = 0; j < 8; j++) {
        const int idx = lane + 32 * j;
        const float4 wv = ((const float4*)w)[idx];
        const float4 bv = ((const float4*)b)[idx];
        const __half2 h0 = __floats2half2_rn((v[j].x - mu) * rs * wv.x + bv.x,
                                             (v[j].y - mu) * rs * wv.y + bv.y);
        const __half2 h1 = __floats2half2_rn((v[j].z - mu) * rs * wv.z + bv.z,
                                             (v[j].w - mu) * rs * wv.w + bv.w);
        uint2 o; o.x = *(const unsigned*)&h0; o.y = *(const unsigned*)&h1;
        yr[idx] = o;
    }
}

#define QT 8
__global__ __launch_bounds__(256)
void attn_kernel(const float* __restrict__ u, __half* __restrict__ out16)
{
    const int q0 = blockIdx.x * QT, h = blockIdx.y, b = blockIdx.z;
    const int tid = threadIdx.x, warp = tid >> 5, lane = tid & 31, q = q0 + warp;

    __shared__ float sq[QT][HDIM], ksm[64][65], vsm[64][65];
    const size_t rb = (size_t)(b * SEQ) * (3 * TDIM);

    for (int i = tid; i < QT * HDIM; i += 256)
        sq[i >> 6][i & 63] = u[rb + (size_t)(q0 + (i >> 6)) * (3 * TDIM) + h * HDIM + (i & 63)];
    __syncthreads();

    float qr[HDIM];
#pragma unroll
    for (int j = 0; j < HDIM; j++) qr[j] = sq[warp][j];

    float m = -1e30f, l = 0.0f, a0 = 0.0f, a1 = 0.0f;

    for (int c0 = 0; c0 < q0 + QT; c0 += 64) {
        for (int i4 = tid; i4 < 1024; i4 += 256) {
            const int r = i4 >> 4, c = (i4 & 15) * 4;
            const size_t base = rb + (size_t)(c0 + r) * (3 * TDIM) + h * HDIM + c;
            const float4 kv = *(const float4*)(u + base + TDIM);
            const float4 vv = *(const float4*)(u + base + 2 * TDIM);
            ksm[r][c] = kv.x; ksm[r][c + 1] = kv.y; ksm[r][c + 2] = kv.z; ksm[r][c + 3] = kv.w;
            vsm[r][c] = vv.x; vsm[r][c + 1] = vv.y; vsm[r][c + 2] = vv.z; vsm[r][c + 3] = vv.w;
        }
        __syncthreads();

        float d0 = 0.0f, d1 = 0.0f;
#pragma unroll
        for (int j = 0; j < HDIM; j++) {
            d0 = fmaf(qr[j], ksm[lane][j], d0);
            d1 = fmaf(qr[j], ksm[lane + 32][j], d1);
        }
        d0 *= 0.125f; d1 *= 0.125f;
        const float s0 = (c0 + lane      <= q) ? d0 : -1e30f;
        const float s1 = (c0 + lane + 32 <= q) ? d1 : -1e30f;

        float cm = fmaxf(s0, s1);
#pragma unroll
        for (int o = 16; o > 0; o >>= 1) cm = fmaxf(cm, __shfl_xor_sync(0xffffffff, cm, o));

        const float mn = fmaxf(m, cm), sc = __expf(m - mn);
        const float p0 = __expf(s0 - mn), p1 = __expf(s1 - mn);
        l = l * sc + p0 + p1;
        a0 *= sc; a1 *= sc;

#pragma unroll 8
        for (int r = 0; r < 32; r++) {
            const float pr = __shfl_sync(0xffffffff, p0, r);
            a0 = fmaf(pr, vsm[r][lane], a0);
            a1 = fmaf(pr, vsm[r][lane + 32], a1);
        }
#pragma unroll 8
        for (int r = 0; r < 32; r++) {
            const float pr = __shfl_sync(0xffffffff, p1, r);
            a0 = fmaf(pr, vsm[r + 32][lane], a0);
            a1 = fmaf(pr, vsm[r + 32][lane + 32], a1);
        }
        m = mn;
        __syncthreads();
    }

#pragma unroll
    for (int o = 16; o > 0; o >>= 1) l += __shfl_xor_sync(0xffffffff, l, o);
    const float inv = 1.0f / l;

    const size_t o = (size_t)(b * SEQ + q) * TDIM + h * HDIM + lane;
    out16[o]      = __float2half_rn(a0 * inv);
    out16[o + 32] = __float2half_rn(a1 * inv);
}

extern "C" void kernel_launch(void* const* d_in, const int* in_sizes, int n_in,
                              void* d_out, int out_size)
{
    (void)in_sizes; (void)n_in; (void)out_size;

    const int*   ids = (const int*)  d_in[0];
    const float* emb = (const float*)d_in[1];
    const float* Wu  = (const float*)d_in[2];
    const float* Wo  = (const float*)d_in[3];
    const float* n1w = (const float*)d_in[4];
    const float* n1b = (const float*)d_in[5];
    const float* n2w = (const float*)d_in[6];
    const float* n2b = (const float*)d_in[7];
    const float* f1w = (const float*)d_in[8];
    const float* f1b = (const float*)d_in[9];
    const float* f2w = (const float*)d_in[10];
    const float* f2b = (const float*)d_in[11];
    const float* fnw = (const float*)d_in[12];
    const float* fnb = (const float*)d_in[13];
    float* out = (float*)d_out;

    float *x, *u; __half *xn16, *at16, *h16, *w16;
    cudaGetSymbolAddress((void**)&x,    g_x);
    cudaGetSymbolAddress((void**)&u,    g_u);
    cudaGetSymbolAddress((void**)&xn16, g_xn16);
    cudaGetSymbolAddress((void**)&at16, g_at16);
    cudaGetSymbolAddress((void**)&h16,  g_h16);
    cudaGetSymbolAddress((void**)&w16,  g_w16);

    cudaFuncSetAttribute(gemm_f16<0>, cudaFuncAttributeMaxDynamicSharedMemorySize, GEMM_SMEM);
    cudaFuncSetAttribute(gemm_f16<1>, cudaFuncAttributeMaxDynamicSharedMemorySize, GEMM_SMEM);
    cudaFuncSetAttribute(gemm_f16<2>, cudaFuncAttributeMaxDynamicSharedMemorySize, GEMM_SMEM);
    cudaFuncSetAttribute(gemm_f16<3>, cudaFuncAttributeMaxDynamicSharedMemorySize, GEMM_SMEM);

    static cudaStream_t s2 = nullptr;
    static cudaEvent_t evF = nullptr, evD = nullptr;
    if (!s2) {
        cudaStreamCreateWithFlags(&s2, cudaStreamNonBlocking);
        cudaEventCreateWithFlags(&evF, cudaEventDisableTiming);
        cudaEventCreateWithFlags(&evD, cudaEventDisableTiming);
    }

    // launches 1..4 (ncu captures #4 = gemm_f16<3>)
    embed_kernel<<<NROWS, 256>>>(ids, emb, x);
    conv16<<<2048, 256>>>(Wu, w16 + WU16, NLAYER * 3 * TDIM * DMODEL / 4);
    layernorm_kernel<<<NROWS / 8, 256>>>(x, n1w, n1b, xn16);
    gemm_f16<3><<<dim3(3 * TDIM / 128, NROWS / 128), 256, GEMM_SMEM>>>(
        xn16, w16 + WU16, nullptr, nullptr, u, nullptr, 3 * TDIM, DMODEL);

    // fork: remaining weight conversions overlap with attention
    cudaEventRecord(evF, 0);
    cudaStreamWaitEvent(s2, evF, 0);
    conv16<<<2048, 256, 0, s2>>>(Wo,  w16 + WO16,  NLAYER * DMODEL * TDIM / 4);
    conv16<<<2048, 256, 0, s2>>>(f1w, w16 + F116,  NLAYER * FFDIM * DMODEL / 4);
    conv16<<<2048, 256, 0, s2>>>(f2w, w16 + F216,  NLAYER * DMODEL * FFDIM / 4);
    conv16<<<2048, 256, 0, s2>>>(emb, w16 + EMB16, VOCAB * DMODEL / 4);
    cudaEventRecord(evD, s2);

    attn_kernel<<<dim3(SEQ / QT, NHEAD, BATCH), 256>>>(u, at16);
    cudaStreamWaitEvent(0, evD, 0);

    for (int l = 0; l < NLAYER; l++) {
        const __half* Wu_l = w16 + WU16 + (size_t)l * 3 * TDIM * DMODEL;
        const __half* Wo_l = w16 + WO16 + (size_t)l * DMODEL * TDIM;
        const __half* f1_l = w16 + F116 + (size_t)l * FFDIM * DMODEL;
        const __half* f2_l = w16 + F216 + (size_t)l * DMODEL * FFDIM;

        if (l > 0) {
            layernorm_kernel<<<NROWS / 8, 256>>>(x, n1w + l * DMODEL, n1b + l * DMODEL, xn16);
            gemm_f16<3><<<dim3(3 * TDIM / 128, NROWS / 128), 256, GEMM_SMEM>>>(
                xn16, Wu_l, nullptr, nullptr, u, nullptr, 3 * TDIM, DMODEL);
            attn_kernel<<<dim3(SEQ / QT, NHEAD, BATCH), 256>>>(u, at16);
        }

        gemm_f16<2><<<dim3(DMODEL / 128, NROWS / 128), 256, GEMM_SMEM>>>(
            at16, Wo_l, nullptr, x, x, nullptr, DMODEL, TDIM);

        layernorm_kernel<<<NROWS / 8, 256>>>(x, n2w + l * DMODEL, n2b + l * DMODEL, xn16);

        gemm_f16<1><<<dim3(FFDIM / 128, NROWS / 128), 256, GEMM_SMEM>>>(
            xn16, f1_l, f1b + (size_t)l * FFDIM, nullptr, nullptr, h16, FFDIM, DMODEL);

        gemm_f16<2><<<dim3(DMODEL / 128, NROWS / 128), 256, GEMM_SMEM>>>(
            h16, f2_l, f2b + (size_t)l * DMODEL, x, x, nullptr, DMODEL, FFDIM);
    }

    layernorm_kernel<<<NROWS / 8, 256>>>(x, fnw, fnb, xn16);

    gemm_f16<0><<<dim3(VOCAB / 128, NROWS / 128), 256, GEMM_SMEM>>>(
        xn16, w16 + EMB16, nullptr, nullptr, out, nullptr, VOCAB, DMODEL);
}

// round 8
// speedup vs baseline: 1.0783x; 1.0783x over previous
#include <cuda_runtime.h>
#include <cuda_fp16.h>
#include <math.h>
#include <stdint.h>

#define BATCH   2
#define SEQ     1024
#define NROWS   (BATCH * SEQ)
#define DMODEL  1024
#define NHEAD   16
#define HDIM    64
#define TDIM    1024
#define FFDIM   4096
#define NLAYER  8
#define VOCAB   32000

#define WU16  0
#define WO16  25165824u
#define F116  33554432u
#define F216  67108864u
#define EMB16 100663296u
#define W16_TOTAL 133431296u

__device__ float  g_x [NROWS * DMODEL];
__device__ float  g_u [NROWS * 3 * TDIM];
__device__ float2 g_rope[SEQ * 32];
__device__ __half g_xn16[NROWS * DMODEL];
__device__ __half g_at16[NROWS * TDIM];
__device__ __half g_h16 [NROWS * FFDIM];
__device__ __half g_w16 [W16_TOTAL];

__device__ __forceinline__ float gelu_exact(float v) {
    return 0.5f * v * (1.0f + erff(v * 0.70710678118654752440f));
}
__device__ __forceinline__ uint32_t s2u(const void* p) {
    uint32_t a;
    asm("{ .reg .u64 t; cvta.to.shared.u64 t, %1; cvt.u32.u64 %0, t; }" : "=r"(a) : "l"(p));
    return a;
}
__device__ __forceinline__ void cp16(uint32_t s, const void* g) {
    asm volatile("cp.async.cg.shared.global [%0], [%1], 16;" :: "r"(s), "l"(g));
}
__device__ __forceinline__ void ldsm4(unsigned* r, uint32_t a) {
    asm volatile("ldmatrix.sync.aligned.m8n8.x4.shared.b16 {%0,%1,%2,%3}, [%4];"
        : "=r"(r[0]), "=r"(r[1]), "=r"(r[2]), "=r"(r[3]) : "r"(a));
}
__device__ __forceinline__ void mma_f16(float* c, const unsigned* a, const unsigned* b) {
    asm volatile(
        "mma.sync.aligned.m16n8k16.row.col.f32.f16.f16.f32 "
        "{%0,%1,%2,%3},{%4,%5,%6,%7},{%8,%9},{%0,%1,%2,%3};"
        : "+f"(c[0]), "+f"(c[1]), "+f"(c[2]), "+f"(c[3])
        : "r"(a[0]), "r"(a[1]), "r"(a[2]), "r"(a[3]), "r"(b[0]), "r"(b[1]));
}
__device__ __forceinline__ void rot(float& a, float& b, float2 cs) {
    const float t0 = a * cs.x - b * cs.y;
    b = b * cs.x + a * cs.y;
    a = t0;
}

// ---------------------------------------------------------------------------
// fp16 GEMM: C[M,N] = A[M,K] @ B[N,K]^T (+ epilogue)
// MODE 0: fp32 C   MODE 1: gelu(acc+bias)->fp16   MODE 2: acc(+bias)+resid->fp32
// MODE 3: rope(acc) via table -> fp32 (QKV)
// BM=BN=128, BK=32, 5-stage cp.async pipeline (prefetch depth 4), ldmatrix.
// smem rows 80B stride (64B data + 16 pad) -> conflict-free.
// ---------------------------------------------------------------------------
template<int MODE>
__global__ __launch_bounds__(256)
void gemm_f16(const __half* __restrict__ A, const __half* __restrict__ B,
              const float* __restrict__ bias, const float* __restrict__ resid,
              float* __restrict__ C, __half* __restrict__ C16,
              const float2* __restrict__ tab, int N, int K)
{
    extern __shared__ __align__(128) char smem[];
    const uint32_t sb = s2u(smem);
    const int tid = threadIdx.x, warp = tid >> 5, lane = tid & 31;
    const int bm = blockIdx.y * 128, bn = blockIdx.x * 128;
    const int moff = (warp & 3) * 32, noff = (warp >> 2) * 64;
    const int g = lane >> 2, t = lane & 3;
    const int nk = K >> 5;
    const int lrow = tid >> 2, lc = tid & 3;

    float acc[2][8][4];
#pragma unroll
    for (int mi = 0; mi < 2; mi++)
#pragma unroll
        for (int ni = 0; ni < 8; ni++)
#pragma unroll
            for (int e = 0; e < 4; e++) acc[mi][ni][e] = 0.0f;

#define LOADST(st, ks) do { \
    const uint32_t so = sb + (uint32_t)(st) * 20480u; \
    const __half* gA = A + (size_t)(bm + lrow) * K + (ks) * 32 + lc * 8; \
    const __half* gB = B + (size_t)(bn + lrow) * K + (ks) * 32 + lc * 8; \
    const uint32_t sA = so + lrow * 80 + lc * 16; \
    const uint32_t sB = sA + 10240u; \
    cp16(sA, gA); cp16(sB, gB); \
    cp16(sA + 64 * 80, gA + (size_t)64 * K); \
    cp16(sB + 64 * 80, gB + (size_t)64 * K); \
} while (0)

#pragma unroll
    for (int pv = 0; pv < 4; pv++) {
        if (pv < nk) LOADST(pv, pv);
        asm volatile("cp.async.commit_group;" ::: "memory");
    }

    const uint32_t aoff = (uint32_t)((moff + (lane & 15)) * 80 + ((lane >> 4) & 1) * 16);
    const uint32_t boff = 10240u +
        (uint32_t)((noff + (lane & 7) + ((lane >> 4) & 1) * 8) * 80 + ((lane >> 3) & 1) * 16);

    for (int ks = 0; ks < nk; ks++) {
        asm volatile("cp.async.wait_group %0;" :: "n"(3) : "memory");
        __syncthreads();
        if (ks + 4 < nk) { LOADST((ks + 4) % 5, ks + 4); }
        asm volatile("cp.async.commit_group;" ::: "memory");

        const uint32_t so = sb + (uint32_t)(ks % 5) * 20480u;
#pragma unroll
        for (int kk = 0; kk < 2; kk++) {
            unsigned a0[4], a1[4], b[4][4];
            ldsm4(a0, so + aoff + kk * 32);
            ldsm4(a1, so + aoff + 16 * 80 + kk * 32);
#pragma unroll
            for (int nj = 0; nj < 4; nj++)
                ldsm4(b[nj], so + boff + nj * 16 * 80 + kk * 32);
#pragma unroll
            for (int nj = 0; nj < 4; nj++) {
                mma_f16(acc[0][2 * nj],     a0, &b[nj][0]);
                mma_f16(acc[0][2 * nj + 1], a0, &b[nj][2]);
                mma_f16(acc[1][2 * nj],     a1, &b[nj][0]);
                mma_f16(acc[1][2 * nj + 1], a1, &b[nj][2]);
            }
        }
    }
#undef LOADST

    if (MODE == 3) {
        const int region = (bn + noff) >> 10;     // 0=q, 1=k, 2=v
        if (region < 2) {
#pragma unroll
            for (int mi = 0; mi < 2; mi++) {
                const int r0 = bm + moff + 16 * mi + g;
                const int s0 = r0 & (SEQ - 1);
#pragma unroll
                for (int ni = 0; ni < 4; ni++) {
                    const int i0 = 8 * ni + 2 * t;
                    const float2 c00 = tab[s0 * 32 + i0];
                    const float2 c01 = tab[s0 * 32 + i0 + 1];
                    const float2 c10 = tab[(s0 + 8) * 32 + i0];
                    const float2 c11 = tab[(s0 + 8) * 32 + i0 + 1];
                    rot(acc[mi][ni][0], acc[mi][ni + 4][0], c00);
                    rot(acc[mi][ni][1], acc[mi][ni + 4][1], c01);
                    rot(acc[mi][ni][2], acc[mi][ni + 4][2], c10);
                    rot(acc[mi][ni][3], acc[mi][ni + 4][3], c11);
                }
            }
        }
    }

#pragma unroll
    for (int mi = 0; mi < 2; mi++) {
        const int r0 = bm + moff + 16 * mi + g;
#pragma unroll
        for (int ni = 0; ni < 8; ni++) {
            const int c = bn + noff + 8 * ni + 2 * t;
            float v00 = acc[mi][ni][0], v01 = acc[mi][ni][1];
            float v10 = acc[mi][ni][2], v11 = acc[mi][ni][3];
            if (MODE == 1) {
                const float b0 = bias[c], b1 = bias[c + 1];
                v00 = gelu_exact(v00 + b0); v01 = gelu_exact(v01 + b1);
                v10 = gelu_exact(v10 + b0); v11 = gelu_exact(v11 + b1);
                *(__half2*)(C16 + (size_t)r0 * N + c)       = __floats2half2_rn(v00, v01);
                *(__half2*)(C16 + (size_t)(r0 + 8) * N + c) = __floats2half2_rn(v10, v11);
            } else {
                if (MODE == 2) {
                    if (bias) {
                        const float b0 = bias[c], b1 = bias[c + 1];
                        v00 += b0; v01 += b1; v10 += b0; v11 += b1;
                    }
                    const float2 rr0 = *(const float2*)(resid + (size_t)r0 * N + c);
                    const float2 rr1 = *(const float2*)(resid + (size_t)(r0 + 8) * N + c);
                    v00 += rr0.x; v01 += rr0.y; v10 += rr1.x; v11 += rr1.y;
                }
                float2 o0; o0.x = v00; o0.y = v01;
                float2 o1; o1.x = v10; o1.y = v11;
                *(float2*)(C + (size_t)r0 * N + c) = o0;
                *(float2*)(C + (size_t)(r0 + 8) * N + c) = o1;
            }
        }
    }
}
#define GEMM_SMEM (5 * 20480)

__global__ void conv16(const float* __restrict__ s, __half* __restrict__ d, int n4)
{
    for (int i = blockIdx.x * blockDim.x + threadIdx.x; i < n4; i += gridDim.x * blockDim.x) {
        const float4 v = ((const float4*)s)[i];
        ((__half2*)d)[2 * i]     = __floats2half2_rn(v.x, v.y);
        ((__half2*)d)[2 * i + 1] = __floats2half2_rn(v.z, v.w);
    }
}

// embed + rope-table build in one kernel (keeps GEMM as launch #4)
__global__ void embed_kernel(const int* __restrict__ ids,
                             const float* __restrict__ emb, float* __restrict__ x,
                             float2* __restrict__ tab)
{
    if (blockIdx.x < NROWS) {
        ((float4*)(x + (size_t)blockIdx.x * DMODEL))[threadIdx.x] =
            ((const float4*)(emb + (size_t)ids[blockIdx.x] * DMODEL))[threadIdx.x];
    } else {
        const int idx = (blockIdx.x - NROWS) * 256 + threadIdx.x;   // < SEQ*32
        const int s = idx >> 5, i = idx & 31;
        const float inv = exp2f(-(float)(2 * i) * (1.0f / 64.0f) * 13.287712379549449f);
        float sn, cs;
        sincosf((float)s * inv, &sn, &cs);
        tab[idx] = make_float2(cs, sn);
    }
}

// warp-per-row LayerNorm -> fp16
__global__ __launch_bounds__(256)
void layernorm_kernel(const float* __restrict__ x, const float* __restrict__ w,
                      const float* __restrict__ b, __half* __restrict__ y16)
{
    const int warp = threadIdx.x >> 5, lane = threadIdx.x & 31;
    const int row = blockIdx.x * 8 + warp;
    const float4* xr = (const float4*)(x + (size_t)row * DMODEL);

    float4 v[8];
    float s = 0.0f;
#pragma unroll
    for (int j = 0; j < 8; j++) {
        v[j] = xr[lane + 32 * j];
        s += v[j].x + v[j].y + v[j].z + v[j].w;
    }
#pragma unroll
    for (int o = 16; o > 0; o >>= 1) s += __shfl_xor_sync(0xffffffff, s, o);
    const float mu = s * (1.0f / DMODEL);

    float q = 0.0f;
#pragma unroll
    for (int j = 0; j < 8; j++) {
        const float a = v[j].x - mu, b2 = v[j].y - mu, c = v[j].z - mu, d = v[j].w - mu;
        q += a * a + b2 * b2 + c * c + d * d;
    }
#pragma unroll
    for (int o = 16; o > 0; o >>= 1) q += __shfl_xor_sync(0xffffffff, q, o);
    const float rs = rsqrtf(q * (1.0f / DMODEL) + 1e-5f);

    uint2* yr = (uint2*)(y16 + (size_t)row * DMODEL);
#pragma unroll
    for (int j = 0; j < 8; j++) {
        const int idx = lane + 32 * j;
        const float4 wv = ((const float4*)w)[idx];
        const float4 bv = ((const float4*)b)[idx];
        const __half2 h0 = __floats2half2_rn((v[j].x - mu) * rs * wv.x + bv.x,
                                             (v[j].y - mu) * rs * wv.y + bv.y);
        const __half2 h1 = __floats2half2_rn((v[j].z - mu) * rs * wv.z + bv.z,
                                             (v[j].w - mu) * rs * wv.w + bv.w);
        uint2 o; o.x = *(const unsigned*)&h0; o.y = *(const unsigned*)&h1;
        yr[idx] = o;
    }
}

#define QT 8
__global__ __launch_bounds__(256)
void attn_kernel(const float* __restrict__ u, __half* __restrict__ out16)
{
    const int q0 = blockIdx.x * QT, h = blockIdx.y, b = blockIdx.z;
    const int tid = threadIdx.x, warp = tid >> 5, lane = tid & 31, q = q0 + warp;

    __shared__ float sq[QT][HDIM], ksm[64][65], vsm[64][65];
    const size_t rb = (size_t)(b * SEQ) * (3 * TDIM);

    for (int i = tid; i < QT * HDIM; i += 256)
        sq[i >> 6][i & 63] = u[rb + (size_t)(q0 + (i >> 6)) * (3 * TDIM) + h * HDIM + (i & 63)];
    __syncthreads();

    float qr[HDIM];
#pragma unroll
    for (int j = 0; j < HDIM; j++) qr[j] = sq[warp][j];

    float m = -1e30f, l = 0.0f, a0 = 0.0f, a1 = 0.0f;

    for (int c0 = 0; c0 < q0 + QT; c0 += 64) {
        for (int i4 = tid; i4 < 1024; i4 += 256) {
            const int r = i4 >> 4, c = (i4 & 15) * 4;
            const size_t base = rb + (size_t)(c0 + r) * (3 * TDIM) + h * HDIM + c;
            const float4 kv = *(const float4*)(u + base + TDIM);
            const float4 vv = *(const float4*)(u + base + 2 * TDIM);
            ksm[r][c] = kv.x; ksm[r][c + 1] = kv.y; ksm[r][c + 2] = kv.z; ksm[r][c + 3] = kv.w;
            vsm[r][c] = vv.x; vsm[r][c + 1] = vv.y; vsm[r][c + 2] = vv.z; vsm[r][c + 3] = vv.w;
        }
        __syncthreads();

        float d0 = 0.0f, d1 = 0.0f;
#pragma unroll
        for (int j = 0; j < HDIM; j++) {
            d0 = fmaf(qr[j], ksm[lane][j], d0);
            d1 = fmaf(qr[j], ksm[lane + 32][j], d1);
        }
        d0 *= 0.125f; d1 *= 0.125f;
        const float s0 = (c0 + lane      <= q) ? d0 : -1e30f;
        const float s1 = (c0 + lane + 32 <= q) ? d1 : -1e30f;

        float cm = fmaxf(s0, s1);
#pragma unroll
        for (int o = 16; o > 0; o >>= 1) cm = fmaxf(cm, __shfl_xor_sync(0xffffffff, cm, o));

        const float mn = fmaxf(m, cm), sc = __expf(m - mn);
        const float p0 = __expf(s0 - mn), p1 = __expf(s1 - mn);
        l = l * sc + p0 + p1;
        a0 *= sc; a1 *= sc;

#pragma unroll 8
        for (int r = 0; r < 32; r++) {
            const float pr = __shfl_sync(0xffffffff, p0, r);
            a0 = fmaf(pr, vsm[r][lane], a0);
            a1 = fmaf(pr, vsm[r][lane + 32], a1);
        }
#pragma unroll 8
        for (int r = 0; r < 32; r++) {
            const float pr = __shfl_sync(0xffffffff, p1, r);
            a0 = fmaf(pr, vsm[r + 32][lane], a0);
            a1 = fmaf(pr, vsm[r + 32][lane + 32], a1);
        }
        m = mn;
        __syncthreads();
    }

#pragma unroll
    for (int o = 16; o > 0; o >>= 1) l += __shfl_xor_sync(0xffffffff, l, o);
    const float inv = 1.0f / l;

    const size_t o = (size_t)(b * SEQ + q) * TDIM + h * HDIM + lane;
    out16[o]      = __float2half_rn(a0 * inv);
    out16[o + 32] = __float2half_rn(a1 * inv);
}

extern "C" void kernel_launch(void* const* d_in, const int* in_sizes, int n_in,
                              void* d_out, int out_size)
{
    (void)in_sizes; (void)n_in; (void)out_size;

    const int*   ids = (const int*)  d_in[0];
    const float* emb = (const float*)d_in[1];
    const float* Wu  = (const float*)d_in[2];
    const float* Wo  = (const float*)d_in[3];
    const float* n1w = (const float*)d_in[4];
    const float* n1b = (const float*)d_in[5];
    const float* n2w = (const float*)d_in[6];
    const float* n2b = (const float*)d_in[7];
    const float* f1w = (const float*)d_in[8];
    const float* f1b = (const float*)d_in[9];
    const float* f2w = (const float*)d_in[10];
    const float* f2b = (const float*)d_in[11];
    const float* fnw = (const float*)d_in[12];
    const float* fnb = (const float*)d_in[13];
    float* out = (float*)d_out;

    float *x, *u; float2* tab; __half *xn16, *at16, *h16, *w16;
    cudaGetSymbolAddress((void**)&x,    g_x);
    cudaGetSymbolAddress((void**)&u,    g_u);
    cudaGetSymbolAddress((void**)&tab,  g_rope);
    cudaGetSymbolAddress((void**)&xn16, g_xn16);
    cudaGetSymbolAddress((void**)&at16, g_at16);
    cudaGetSymbolAddress((void**)&h16,  g_h16);
    cudaGetSymbolAddress((void**)&w16,  g_w16);

    cudaFuncSetAttribute(gemm_f16<0>, cudaFuncAttributeMaxDynamicSharedMemorySize, GEMM_SMEM);
    cudaFuncSetAttribute(gemm_f16<1>, cudaFuncAttributeMaxDynamicSharedMemorySize, GEMM_SMEM);
    cudaFuncSetAttribute(gemm_f16<2>, cudaFuncAttributeMaxDynamicSharedMemorySize, GEMM_SMEM);
    cudaFuncSetAttribute(gemm_f16<3>, cudaFuncAttributeMaxDynamicSharedMemorySize, GEMM_SMEM);

    // 1..4: embed+tab, convWu, LN, QKV-GEMM (launch #4 -> ncu)
    embed_kernel<<<NROWS + SEQ * 32 / 256, 256>>>(ids, emb, x, tab);
    conv16<<<2048, 256>>>(Wu, w16 + WU16, NLAYER * 3 * TDIM * DMODEL / 4);
    layernorm_kernel<<<NROWS / 8, 256>>>(x, n1w, n1b, xn16);
    gemm_f16<3><<<dim3(3 * TDIM / 128, NROWS / 128), 256, GEMM_SMEM>>>(
        xn16, w16 + WU16, nullptr, nullptr, u, nullptr, tab, 3 * TDIM, DMODEL);

    conv16<<<2048, 256>>>(Wo,  w16 + WO16,  NLAYER * DMODEL * TDIM / 4);
    conv16<<<2048, 256>>>(f1w, w16 + F116,  NLAYER * FFDIM * DMODEL / 4);
    conv16<<<2048, 256>>>(f2w, w16 + F216,  NLAYER * DMODEL * FFDIM / 4);
    conv16<<<2048, 256>>>(emb, w16 + EMB16, VOCAB * DMODEL / 4);

    attn_kernel<<<dim3(SEQ / QT, NHEAD, BATCH), 256>>>(u, at16);

    for (int l = 0; l < NLAYER; l++) {
        const __half* Wu_l = w16 + WU16 + (size_t)l * 3 * TDIM * DMODEL;
        const __half* Wo_l = w16 + WO16 + (size_t)l * DMODEL * TDIM;
        const __half* f1_l = w16 + F116 + (size_t)l * FFDIM * DMODEL;
        const __half* f2_l = w16 + F216 + (size_t)l * DMODEL * FFDIM;

        if (l > 0) {
            layernorm_kernel<<<NROWS / 8, 256>>>(x, n1w + l * DMODEL, n1b + l * DMODEL, xn16);
            gemm_f16<3><<<dim3(3 * TDIM / 128, NROWS / 128), 256, GEMM_SMEM>>>(
                xn16, Wu_l, nullptr, nullptr, u, nullptr, tab, 3 * TDIM, DMODEL);
            attn_kernel<<<dim3(SEQ / QT, NHEAD, BATCH), 256>>>(u, at16);
        }

        gemm_f16<2><<<dim3(DMODEL / 128, NROWS / 128), 256, GEMM_SMEM>>>(
            at16, Wo_l, nullptr, x, x, nullptr, nullptr, DMODEL, TDIM);

        layernorm_kernel<<<NROWS / 8, 256>>>(x, n2w + l * DMODEL, n2b + l * DMODEL, xn16);

        gemm_f16<1><<<dim3(FFDIM / 128, NROWS / 128), 256, GEMM_SMEM>>>(
            xn16, f1_l, f1b + (size_t)l * FFDIM, nullptr, nullptr, h16, nullptr, FFDIM, DMODEL);

        gemm_f16<2><<<dim3(DMODEL / 128, NROWS / 128), 256, GEMM_SMEM>>>(
            h16, f2_l, f2b + (size_t)l * DMODEL, x, x, nullptr, nullptr, DMODEL, FFDIM);
    }

    layernorm_kernel<<<NROWS / 8, 256>>>(x, fnw, fnb, xn16);

    gemm_f16<0><<<dim3(VOCAB / 128, NROWS / 128), 256, GEMM_SMEM>>>(
        xn16, w16 + EMB16, nullptr, nullptr, out, nullptr, nullptr, VOCAB, DMODEL);
}

// round 9
// speedup vs baseline: 2.4665x; 2.2874x over previous
#include <cuda_runtime.h>
#include <cuda_fp16.h>
#include <math.h>
#include <stdint.h>

#define BATCH   2
#define SEQ     1024
#define NROWS   (BATCH * SEQ)
#define DMODEL  1024
#define NHEAD   16
#define HDIM    64
#define TDIM    1024
#define FFDIM   4096
#define NLAYER  8
#define VOCAB   32000

#define WU16  0
#define WO16  25165824u
#define F116  33554432u
#define F216  67108864u
#define EMB16 100663296u
#define W16_TOTAL 133431296u

__device__ float  g_x [NROWS * DMODEL];
__device__ float2 g_rope[SEQ * 32];
__device__ __half g_u16 [NROWS * 3 * TDIM];
__device__ __half g_xn16[NROWS * DMODEL];
__device__ __half g_at16[NROWS * TDIM];
__device__ __half g_h16 [NROWS * FFDIM];
__device__ __half g_w16 [W16_TOTAL];

__device__ __forceinline__ float gelu_exact(float v) {
    return 0.5f * v * (1.0f + erff(v * 0.70710678118654752440f));
}
__device__ __forceinline__ uint32_t s2u(const void* p) {
    uint32_t a;
    asm("{ .reg .u64 t; cvta.to.shared.u64 t, %1; cvt.u32.u64 %0, t; }" : "=r"(a) : "l"(p));
    return a;
}
__device__ __forceinline__ void cp16(uint32_t s, const void* g) {
    asm volatile("cp.async.cg.shared.global [%0], [%1], 16;" :: "r"(s), "l"(g));
}
__device__ __forceinline__ void ldsm4(unsigned* r, uint32_t a) {
    asm volatile("ldmatrix.sync.aligned.m8n8.x4.shared.b16 {%0,%1,%2,%3}, [%4];"
        : "=r"(r[0]), "=r"(r[1]), "=r"(r[2]), "=r"(r[3]) : "r"(a));
}
__device__ __forceinline__ void ldsm4t(unsigned* r, uint32_t a) {
    asm volatile("ldmatrix.sync.aligned.m8n8.x4.trans.shared.b16 {%0,%1,%2,%3}, [%4];"
        : "=r"(r[0]), "=r"(r[1]), "=r"(r[2]), "=r"(r[3]) : "r"(a));
}
__device__ __forceinline__ void mma_f16(float* c, const unsigned* a, const unsigned* b) {
    asm volatile(
        "mma.sync.aligned.m16n8k16.row.col.f32.f16.f16.f32 "
        "{%0,%1,%2,%3},{%4,%5,%6,%7},{%8,%9},{%0,%1,%2,%3};"
        : "+f"(c[0]), "+f"(c[1]), "+f"(c[2]), "+f"(c[3])
        : "r"(a[0]), "r"(a[1]), "r"(a[2]), "r"(a[3]), "r"(b[0]), "r"(b[1]));
}
__device__ __forceinline__ void rot(float& a, float& b, float2 cs) {
    const float t0 = a * cs.x - b * cs.y;
    b = b * cs.x + a * cs.y;
    a = t0;
}
__device__ __forceinline__ unsigned packh2(float a, float b) {
    __half2 h = __floats2half2_rn(a, b);
    return *(unsigned*)&h;
}

// ---------------------------------------------------------------------------
// fp16 GEMM (round-5 proven config): C = A @ B^T
// MODE 0: fp32 C   MODE 1: gelu(acc+bias)->fp16   MODE 2: acc(+bias)+resid->fp32
// MODE 3: rope(acc) via table -> fp16 C16 (QKV)
// BM=BN=128, BK=32, 3-stage cp.async, ldmatrix feeds, 80B smem row stride.
// ---------------------------------------------------------------------------
template<int MODE>
__global__ __launch_bounds__(256)
void gemm_f16(const __half* __restrict__ A, const __half* __restrict__ B,
              const float* __restrict__ bias, const float* __restrict__ resid,
              float* __restrict__ C, __half* __restrict__ C16,
              const float2* __restrict__ tab, int N, int K)
{
    extern __shared__ __align__(128) char smem[];
    const uint32_t sb = s2u(smem);
    const int tid = threadIdx.x, warp = tid >> 5, lane = tid & 31;
    const int bm = blockIdx.y * 128, bn = blockIdx.x * 128;
    const int moff = (warp & 3) * 32, noff = (warp >> 2) * 64;
    const int g = lane >> 2, t = lane & 3;
    const int nk = K >> 5;
    const int lrow = tid >> 2, lc = tid & 3;

    float acc[2][8][4];
#pragma unroll
    for (int mi = 0; mi < 2; mi++)
#pragma unroll
        for (int ni = 0; ni < 8; ni++)
#pragma unroll
            for (int e = 0; e < 4; e++) acc[mi][ni][e] = 0.0f;

#define LOADST(st, ks) do { \
    const uint32_t so = sb + (uint32_t)(st) * 20480u; \
    const __half* gA = A + (size_t)(bm + lrow) * K + (ks) * 32 + lc * 8; \
    const __half* gB = B + (size_t)(bn + lrow) * K + (ks) * 32 + lc * 8; \
    const uint32_t sA = so + lrow * 80 + lc * 16; \
    const uint32_t sB = sA + 10240u; \
    cp16(sA, gA); cp16(sB, gB); \
    cp16(sA + 64 * 80, gA + (size_t)64 * K); \
    cp16(sB + 64 * 80, gB + (size_t)64 * K); \
} while (0)

    LOADST(0, 0);
    asm volatile("cp.async.commit_group;" ::: "memory");
    if (nk > 1) LOADST(1, 1);
    asm volatile("cp.async.commit_group;" ::: "memory");

    const uint32_t aoff = (uint32_t)((moff + (lane & 15)) * 80 + ((lane >> 4) & 1) * 16);
    const uint32_t boff = 10240u +
        (uint32_t)((noff + (lane & 7) + ((lane >> 4) & 1) * 8) * 80 + ((lane >> 3) & 1) * 16);

    for (int ks = 0; ks < nk; ks++) {
        asm volatile("cp.async.wait_group %0;" :: "n"(1) : "memory");
        __syncthreads();
        if (ks + 2 < nk) { LOADST((ks + 2) % 3, ks + 2); }
        asm volatile("cp.async.commit_group;" ::: "memory");

        const uint32_t so = sb + (uint32_t)(ks % 3) * 20480u;
#pragma unroll
        for (int kk = 0; kk < 2; kk++) {
            unsigned a0[4], a1[4], b[4][4];
            ldsm4(a0, so + aoff + kk * 32);
            ldsm4(a1, so + aoff + 16 * 80 + kk * 32);
#pragma unroll
            for (int nj = 0; nj < 4; nj++)
                ldsm4(b[nj], so + boff + nj * 16 * 80 + kk * 32);
#pragma unroll
            for (int nj = 0; nj < 4; nj++) {
                mma_f16(acc[0][2 * nj],     a0, &b[nj][0]);
                mma_f16(acc[0][2 * nj + 1], a0, &b[nj][2]);
                mma_f16(acc[1][2 * nj],     a1, &b[nj][0]);
                mma_f16(acc[1][2 * nj + 1], a1, &b[nj][2]);
            }
        }
    }
#undef LOADST

    if (MODE == 3) {
        const int region = (bn + noff) >> 10;     // 0=q, 1=k, 2=v
        if (region < 2) {
#pragma unroll
            for (int mi = 0; mi < 2; mi++) {
                const int r0 = bm + moff + 16 * mi + g;
                const int s0 = r0 & (SEQ - 1);
#pragma unroll
                for (int ni = 0; ni < 4; ni++) {
                    const int i0 = 8 * ni + 2 * t;
                    const float2 c00 = tab[s0 * 32 + i0];
                    const float2 c01 = tab[s0 * 32 + i0 + 1];
                    const float2 c10 = tab[(s0 + 8) * 32 + i0];
                    const float2 c11 = tab[(s0 + 8) * 32 + i0 + 1];
                    rot(acc[mi][ni][0], acc[mi][ni + 4][0], c00);
                    rot(acc[mi][ni][1], acc[mi][ni + 4][1], c01);
                    rot(acc[mi][ni][2], acc[mi][ni + 4][2], c10);
                    rot(acc[mi][ni][3], acc[mi][ni + 4][3], c11);
                }
            }
        }
    }

#pragma unroll
    for (int mi = 0; mi < 2; mi++) {
        const int r0 = bm + moff + 16 * mi + g;
#pragma unroll
        for (int ni = 0; ni < 8; ni++) {
            const int c = bn + noff + 8 * ni + 2 * t;
            float v00 = acc[mi][ni][0], v01 = acc[mi][ni][1];
            float v10 = acc[mi][ni][2], v11 = acc[mi][ni][3];
            if (MODE == 1 || MODE == 3) {
                if (MODE == 1) {
                    const float b0 = bias[c], b1 = bias[c + 1];
                    v00 = gelu_exact(v00 + b0); v01 = gelu_exact(v01 + b1);
                    v10 = gelu_exact(v10 + b0); v11 = gelu_exact(v11 + b1);
                }
                *(__half2*)(C16 + (size_t)r0 * N + c)       = __floats2half2_rn(v00, v01);
                *(__half2*)(C16 + (size_t)(r0 + 8) * N + c) = __floats2half2_rn(v10, v11);
            } else {
                if (MODE == 2) {
                    if (bias) {
                        const float b0 = bias[c], b1 = bias[c + 1];
                        v00 += b0; v01 += b1; v10 += b0; v11 += b1;
                    }
                    const float2 rr0 = *(const float2*)(resid + (size_t)r0 * N + c);
                    const float2 rr1 = *(const float2*)(resid + (size_t)(r0 + 8) * N + c);
                    v00 += rr0.x; v01 += rr0.y; v10 += rr1.x; v11 += rr1.y;
                }
                float2 o0; o0.x = v00; o0.y = v01;
                float2 o1; o1.x = v10; o1.y = v11;
                *(float2*)(C + (size_t)r0 * N + c) = o0;
                *(float2*)(C + (size_t)(r0 + 8) * N + c) = o1;
            }
        }
    }
}
#define GEMM_SMEM (3 * 20480)

// ---------------------------------------------------------------------------
// MMA flash attention: 64 queries/block, 4 warps, fp16 in/out, fp32 softmax.
// grid (SEQ/64, NHEAD, BATCH), 128 threads.
// ---------------------------------------------------------------------------
__global__ __launch_bounds__(128)
void attn_mma(const __half* __restrict__ U, __half* __restrict__ O)
{
    const int q0 = blockIdx.x * 64, h = blockIdx.y, b = blockIdx.z;
    const int tid = threadIdx.x, warp = tid >> 5, lane = tid & 31;
    const int g = lane >> 2, t = lane & 3;

    __shared__ __half qs[64 * 72];
    __shared__ __half ks[64 * 72];
    __shared__ __half vs[64 * 72];
    const uint32_t qb = s2u(qs), kb = s2u(ks), vb = s2u(vs);

    const __half* Ub = U + (size_t)(b * SEQ) * 3072 + h * 64;

    // load Q tile (64 rows x 128B), 2 threads per row
    {
        const int r = tid >> 1;
        const int sg = (tid & 1) * 64;                 // byte segment
        const __half* gq = Ub + (size_t)(q0 + r) * 3072 + sg / 2;
        const uint32_t sq = qb + r * 144 + sg;
        cp16(sq, gq); cp16(sq + 16, gq + 8);
        cp16(sq + 32, gq + 16); cp16(sq + 48, gq + 24);
    }
    asm volatile("cp.async.commit_group;" ::: "memory");
    asm volatile("cp.async.wait_group 0;" ::: "memory");
    __syncthreads();

    // hoist Q fragments (pre-scaled by 1/sqrt(64) = 0.125, exact in fp16)
    unsigned qf[4][4];
    {
        const uint32_t qa = qb + (16 * warp + (lane & 15)) * 144 + ((lane >> 4) & 1) * 16;
        const __half2 sc = __floats2half2_rn(0.125f, 0.125f);
#pragma unroll
        for (int kk = 0; kk < 4; kk++) {
            ldsm4(qf[kk], qa + kk * 32);
#pragma unroll
            for (int e = 0; e < 4; e++) {
                __half2 v = *(__half2*)&qf[kk][e];
                v = __hmul2(v, sc);
                qf[kk][e] = *(unsigned*)&v;
            }
        }
    }

    float o[8][4];
#pragma unroll
    for (int d = 0; d < 8; d++)
#pragma unroll
        for (int e = 0; e < 4; e++) o[d][e] = 0.0f;
    float m0 = -1e30f, m1 = -1e30f, l0 = 0.0f, l1 = 0.0f;
    const int row0 = q0 + 16 * warp + g;

    for (int c0 = 0; c0 <= q0; c0 += 64) {
        // load K,V chunk: thread -> one row (128B = 8 cp16)
        {
            const int r = tid & 63;
            const __half* gp = Ub + (size_t)(c0 + r) * 3072 + ((tid >= 64) ? 2048 : 1024);
            const uint32_t sp = ((tid >= 64) ? vb : kb) + r * 144;
#pragma unroll
            for (int i = 0; i < 8; i++) cp16(sp + 16 * i, gp + 8 * i);
        }
        asm volatile("cp.async.commit_group;" ::: "memory");
        asm volatile("cp.async.wait_group 0;" ::: "memory");
        __syncthreads();

        // scores S = Q K^T : 8 n8-tiles
        float s[8][4];
#pragma unroll
        for (int j = 0; j < 8; j++)
#pragma unroll
            for (int e = 0; e < 4; e++) s[j][e] = 0.0f;
#pragma unroll
        for (int kk = 0; kk < 4; kk++) {
            unsigned bf[4][4];
#pragma unroll
            for (int nj = 0; nj < 4; nj++)
                ldsm4(bf[nj], kb + (nj * 16 + (lane & 7) + ((lane >> 4) & 1) * 8) * 144
                                + ((lane >> 3) & 1) * 16 + kk * 32);
#pragma unroll
            for (int nj = 0; nj < 4; nj++) {
                mma_f16(s[2 * nj],     qf[kk], &bf[nj][0]);
                mma_f16(s[2 * nj + 1], qf[kk], &bf[nj][2]);
            }
        }

        // causal mask (diagonal chunk only)
        if (c0 == q0) {
#pragma unroll
            for (int j = 0; j < 8; j++) {
                const int cb = c0 + 8 * j + 2 * t;
                if (cb     > row0)     s[j][0] = -1e30f;
                if (cb + 1 > row0)     s[j][1] = -1e30f;
                if (cb     > row0 + 8) s[j][2] = -1e30f;
                if (cb + 1 > row0 + 8) s[j][3] = -1e30f;
            }
        }

        // online softmax
        float cm0 = -1e30f, cm1 = -1e30f;
#pragma unroll
        for (int j = 0; j < 8; j++) {
            cm0 = fmaxf(cm0, fmaxf(s[j][0], s[j][1]));
            cm1 = fmaxf(cm1, fmaxf(s[j][2], s[j][3]));
        }
        cm0 = fmaxf(cm0, __shfl_xor_sync(0xffffffff, cm0, 1));
        cm0 = fmaxf(cm0, __shfl_xor_sync(0xffffffff, cm0, 2));
        cm1 = fmaxf(cm1, __shfl_xor_sync(0xffffffff, cm1, 1));
        cm1 = fmaxf(cm1, __shfl_xor_sync(0xffffffff, cm1, 2));
        const float nm0 = fmaxf(m0, cm0), nm1 = fmaxf(m1, cm1);
        const float f0 = __expf(m0 - nm0), f1 = __expf(m1 - nm1);
        m0 = nm0; m1 = nm1;

        unsigned pf[4][4];
        float sum0 = 0.0f, sum1 = 0.0f;
#pragma unroll
        for (int nj = 0; nj < 4; nj++) {
            const float pa0 = __expf(s[2 * nj][0] - nm0), pa1 = __expf(s[2 * nj][1] - nm0);
            const float pa2 = __expf(s[2 * nj][2] - nm1), pa3 = __expf(s[2 * nj][3] - nm1);
            const float pb0 = __expf(s[2 * nj + 1][0] - nm0), pb1 = __expf(s[2 * nj + 1][1] - nm0);
            const float pb2 = __expf(s[2 * nj + 1][2] - nm1), pb3 = __expf(s[2 * nj + 1][3] - nm1);
            sum0 += pa0 + pa1 + pb0 + pb1;
            sum1 += pa2 + pa3 + pb2 + pb3;
            pf[nj][0] = packh2(pa0, pa1);
            pf[nj][1] = packh2(pa2, pa3);
            pf[nj][2] = packh2(pb0, pb1);
            pf[nj][3] = packh2(pb2, pb3);
        }
        sum0 += __shfl_xor_sync(0xffffffff, sum0, 1);
        sum0 += __shfl_xor_sync(0xffffffff, sum0, 2);
        sum1 += __shfl_xor_sync(0xffffffff, sum1, 1);
        sum1 += __shfl_xor_sync(0xffffffff, sum1, 2);
        l0 = l0 * f0 + sum0;
        l1 = l1 * f1 + sum1;

#pragma unroll
        for (int d = 0; d < 8; d++) {
            o[d][0] *= f0; o[d][1] *= f0; o[d][2] *= f1; o[d][3] *= f1;
        }

        // O += P V : V^T fragments via ldsm.trans
#pragma unroll
        for (int kk = 0; kk < 4; kk++) {
            unsigned vf[4][4];
#pragma unroll
            for (int dj = 0; dj < 4; dj++)
                ldsm4t(vf[dj], vb + (kk * 16 + (lane & 7) + ((lane >> 3) & 1) * 8) * 144
                                 + (dj * 16 + ((lane >> 4) & 1) * 8) * 2);
#pragma unroll
            for (int dj = 0; dj < 4; dj++) {
                mma_f16(o[2 * dj],     pf[kk], &vf[dj][0]);
                mma_f16(o[2 * dj + 1], pf[kk], &vf[dj][2]);
            }
        }
        __syncthreads();
    }

    const float il0 = 1.0f / l0, il1 = 1.0f / l1;
    __half* Ob = O + (size_t)(b * SEQ + row0) * TDIM + h * 64;
#pragma unroll
    for (int dj = 0; dj < 8; dj++) {
        const int c = 8 * dj + 2 * t;
        *(__half2*)(Ob + c)            = __floats2half2_rn(o[dj][0] * il0, o[dj][1] * il0);
        *(__half2*)(Ob + 8 * TDIM + c) = __floats2half2_rn(o[dj][2] * il1, o[dj][3] * il1);
    }
}

// ---------------------------------------------------------------------------
__global__ void conv16(const float* __restrict__ s, __half* __restrict__ d, int n4)
{
    for (int i = blockIdx.x * blockDim.x + threadIdx.x; i < n4; i += gridDim.x * blockDim.x) {
        const float4 v = ((const float4*)s)[i];
        ((__half2*)d)[2 * i]     = __floats2half2_rn(v.x, v.y);
        ((__half2*)d)[2 * i + 1] = __floats2half2_rn(v.z, v.w);
    }
}

// prep: embed + rope table + convWu in one launch (keeps attn as launch #4)
__global__ void prep_kernel(const int* __restrict__ ids, const float* __restrict__ emb,
                            float* __restrict__ x, float2* __restrict__ tab,
                            const float* __restrict__ Wu, __half* __restrict__ wu16)
{
    if (blockIdx.x < NROWS) {
        ((float4*)(x + (size_t)blockIdx.x * DMODEL))[threadIdx.x] =
            ((const float4*)(emb + (size_t)ids[blockIdx.x] * DMODEL))[threadIdx.x];
    } else if (blockIdx.x < NROWS + 128) {
        const int idx = (blockIdx.x - NROWS) * 256 + threadIdx.x;
        const int s = idx >> 5, i = idx & 31;
        const float inv = exp2f(-(float)(2 * i) * (1.0f / 64.0f) * 13.287712379549449f);
        float sn, cs;
        sincosf((float)s * inv, &sn, &cs);
        tab[idx] = make_float2(cs, sn);
    } else {
        const int n4 = NLAYER * 3 * TDIM * DMODEL / 4;
        for (int i = (blockIdx.x - NROWS - 128) * 256 + threadIdx.x; i < n4; i += 2048 * 256) {
            const float4 v = ((const float4*)Wu)[i];
            ((__half2*)wu16)[2 * i]     = __floats2half2_rn(v.x, v.y);
            ((__half2*)wu16)[2 * i + 1] = __floats2half2_rn(v.z, v.w);
        }
    }
}

// block-per-row LayerNorm -> fp16 (round-5 proven)
__global__ __launch_bounds__(256)
void layernorm_kernel(const float* __restrict__ x, const float* __restrict__ w,
                      const float* __restrict__ b, __half* __restrict__ y16)
{
    const int row = blockIdx.x, tid = threadIdx.x;
    __shared__ float red[256];

    const float4 v = ((const float4*)(x + (size_t)row * DMODEL))[tid];
    red[tid] = v.x + v.y + v.z + v.w; __syncthreads();
    for (int k = 128; k > 0; k >>= 1) { if (tid < k) red[tid] += red[tid + k]; __syncthreads(); }
    const float mu = red[0] * (1.0f / DMODEL); __syncthreads();

    const float dx = v.x - mu, dy = v.y - mu, dz = v.z - mu, dw = v.w - mu;
    red[tid] = dx * dx + dy * dy + dz * dz + dw * dw; __syncthreads();
    for (int k = 128; k > 0; k >>= 1) { if (tid < k) red[tid] += red[tid + k]; __syncthreads(); }
    const float rs = rsqrtf(red[0] * (1.0f / DMODEL) + 1e-5f);

    const float4 wv = ((const float4*)w)[tid];
    const float4 bv = ((const float4*)b)[tid];
    const __half2 h0 = __floats2half2_rn(dx * rs * wv.x + bv.x, dy * rs * wv.y + bv.y);
    const __half2 h1 = __floats2half2_rn(dz * rs * wv.z + bv.z, dw * rs * wv.w + bv.w);
    uint2 out; out.x = *(const unsigned*)&h0; out.y = *(const unsigned*)&h1;
    ((uint2*)(y16 + (size_t)row * DMODEL))[tid] = out;
}

extern "C" void kernel_launch(void* const* d_in, const int* in_sizes, int n_in,
                              void* d_out, int out_size)
{
    (void)in_sizes; (void)n_in; (void)out_size;

    const int*   ids = (const int*)  d_in[0];
    const float* emb = (const float*)d_in[1];
    const float* Wu  = (const float*)d_in[2];
    const float* Wo  = (const float*)d_in[3];
    const float* n1w = (const float*)d_in[4];
    const float* n1b = (const float*)d_in[5];
    const float* n2w = (const float*)d_in[6];
    const float* n2b = (const float*)d_in[7];
    const float* f1w = (const float*)d_in[8];
    const float* f1b = (const float*)d_in[9];
    const float* f2w = (const float*)d_in[10];
    const float* f2b = (const float*)d_in[11];
    const float* fnw = (const float*)d_in[12];
    const float* fnb = (const float*)d_in[13];
    float* out = (float*)d_out;

    float *x; float2* tab; __half *u16, *xn16, *at16, *h16, *w16;
    cudaGetSymbolAddress((void**)&x,    g_x);
    cudaGetSymbolAddress((void**)&tab,  g_rope);
    cudaGetSymbolAddress((void**)&u16,  g_u16);
    cudaGetSymbolAddress((void**)&xn16, g_xn16);
    cudaGetSymbolAddress((void**)&at16, g_at16);
    cudaGetSymbolAddress((void**)&h16,  g_h16);
    cudaGetSymbolAddress((void**)&w16,  g_w16);

    cudaFuncSetAttribute(gemm_f16<0>, cudaFuncAttributeMaxDynamicSharedMemorySize, GEMM_SMEM);
    cudaFuncSetAttribute(gemm_f16<1>, cudaFuncAttributeMaxDynamicSharedMemorySize, GEMM_SMEM);
    cudaFuncSetAttribute(gemm_f16<2>, cudaFuncAttributeMaxDynamicSharedMemorySize, GEMM_SMEM);
    cudaFuncSetAttribute(gemm_f16<3>, cudaFuncAttributeMaxDynamicSharedMemorySize, GEMM_SMEM);

    // 1: prep (embed + rope table + convWu)   2: LN   3: QKV   4: attn (ncu)
    prep_kernel<<<NROWS + 128 + 2048, 256>>>(ids, emb, x, tab, Wu, w16 + WU16);
    layernorm_kernel<<<NROWS, 256>>>(x, n1w, n1b, xn16);
    gemm_f16<3><<<dim3(3 * TDIM / 128, NROWS / 128), 256, GEMM_SMEM>>>(
        xn16, w16 + WU16, nullptr, nullptr, nullptr, u16, tab, 3 * TDIM, DMODEL);
    attn_mma<<<dim3(SEQ / 64, NHEAD, BATCH), 128>>>(u16, at16);

    conv16<<<2048, 256>>>(Wo,  w16 + WO16,  NLAYER * DMODEL * TDIM / 4);
    conv16<<<2048, 256>>>(f1w, w16 + F116,  NLAYER * FFDIM * DMODEL / 4);
    conv16<<<2048, 256>>>(f2w, w16 + F216,  NLAYER * DMODEL * FFDIM / 4);
    conv16<<<2048, 256>>>(emb, w16 + EMB16, VOCAB * DMODEL / 4);

    for (int l = 0; l < NLAYER; l++) {
        const __half* Wu_l = w16 + WU16 + (size_t)l * 3 * TDIM * DMODEL;
        const __half* Wo_l = w16 + WO16 + (size_t)l * DMODEL * TDIM;
        const __half* f1_l = w16 + F116 + (size_t)l * FFDIM * DMODEL;
        const __half* f2_l = w16 + F216 + (size_t)l * DMODEL * FFDIM;

        if (l > 0) {
            layernorm_kernel<<<NROWS, 256>>>(x, n1w + l * DMODEL, n1b + l * DMODEL, xn16);
            gemm_f16<3><<<dim3(3 * TDIM / 128, NROWS / 128), 256, GEMM_SMEM>>>(
                xn16, Wu_l, nullptr, nullptr, nullptr, u16, tab, 3 * TDIM, DMODEL);
            attn_mma<<<dim3(SEQ / 64, NHEAD, BATCH), 128>>>(u16, at16);
        }

        gemm_f16<2><<<dim3(DMODEL / 128, NROWS / 128), 256, GEMM_SMEM>>>(
            at16, Wo_l, nullptr, x, x, nullptr, nullptr, DMODEL, TDIM);

        layernorm_kernel<<<NROWS, 256>>>(x, n2w + l * DMODEL, n2b + l * DMODEL, xn16);

        gemm_f16<1><<<dim3(FFDIM / 128, NROWS / 128), 256, GEMM_SMEM>>>(
            xn16, f1_l, f1b + (size_t)l * FFDIM, nullptr, nullptr, h16, nullptr, FFDIM, DMODEL);

        gemm_f16<2><<<dim3(DMODEL / 128, NROWS / 128), 256, GEMM_SMEM>>>(
            h16, f2_l, f2b + (size_t)l * DMODEL, x, x, nullptr, nullptr, DMODEL, FFDIM);
    }

    layernorm_kernel<<<NROWS, 256>>>(x, fnw, fnb, xn16);

    gemm_f16<0><<<dim3(VOCAB / 128, NROWS / 128), 256, GEMM_SMEM>>>(
        xn16, w16 + EMB16, nullptr, nullptr, out, nullptr, nullptr, VOCAB, DMODEL);
}

// round 10
// speedup vs baseline: 2.5372x; 1.0287x over previous
#include <cuda_runtime.h>
#include <cuda_fp16.h>
#include <math.h>
#include <stdint.h>

#define BATCH   2
#define SEQ     1024
#define NROWS   (BATCH * SEQ)
#define DMODEL  1024
#define NHEAD   16
#define HDIM    64
#define TDIM    1024
#define FFDIM   4096
#define NLAYER  8
#define VOCAB   32000

#define WU16  0
#define WO16  25165824u
#define F116  33554432u
#define F216  67108864u
#define EMB16 100663296u
#define W16_TOTAL 133431296u

__device__ float  g_x [NROWS * DMODEL];
__device__ float2 g_rope[SEQ * 32];
__device__ __half g_u16 [NROWS * 3 * TDIM];
__device__ __half g_xn16[NROWS * DMODEL];
__device__ __half g_at16[NROWS * TDIM];
__device__ __half g_h16 [NROWS * FFDIM];
__device__ __half g_w16 [W16_TOTAL];

__device__ __forceinline__ float gelu_exact(float v) {
    return 0.5f * v * (1.0f + erff(v * 0.70710678118654752440f));
}
__device__ __forceinline__ uint32_t s2u(const void* p) {
    uint32_t a;
    asm("{ .reg .u64 t; cvta.to.shared.u64 t, %1; cvt.u32.u64 %0, t; }" : "=r"(a) : "l"(p));
    return a;
}
__device__ __forceinline__ void cp16(uint32_t s, const void* g) {
    asm volatile("cp.async.cg.shared.global [%0], [%1], 16;" :: "r"(s), "l"(g));
}
__device__ __forceinline__ void ldsm4(unsigned* r, uint32_t a) {
    asm volatile("ldmatrix.sync.aligned.m8n8.x4.shared.b16 {%0,%1,%2,%3}, [%4];"
        : "=r"(r[0]), "=r"(r[1]), "=r"(r[2]), "=r"(r[3]) : "r"(a));
}
__device__ __forceinline__ void ldsm4t(unsigned* r, uint32_t a) {
    asm volatile("ldmatrix.sync.aligned.m8n8.x4.trans.shared.b16 {%0,%1,%2,%3}, [%4];"
        : "=r"(r[0]), "=r"(r[1]), "=r"(r[2]), "=r"(r[3]) : "r"(a));
}
__device__ __forceinline__ void mma_f16(float* c, const unsigned* a, const unsigned* b) {
    asm volatile(
        "mma.sync.aligned.m16n8k16.row.col.f32.f16.f16.f32 "
        "{%0,%1,%2,%3},{%4,%5,%6,%7},{%8,%9},{%0,%1,%2,%3};"
        : "+f"(c[0]), "+f"(c[1]), "+f"(c[2]), "+f"(c[3])
        : "r"(a[0]), "r"(a[1]), "r"(a[2]), "r"(a[3]), "r"(b[0]), "r"(b[1]));
}
__device__ __forceinline__ void rot(float& a, float& b, float2 cs) {
    const float t0 = a * cs.x - b * cs.y;
    b = b * cs.x + a * cs.y;
    a = t0;
}
__device__ __forceinline__ unsigned packh2(float a, float b) {
    __half2 h = __floats2half2_rn(a, b);
    return *(unsigned*)&h;
}

// ---------------------------------------------------------------------------
// fp16 GEMM (proven config): C = A @ B^T
// MODE 0: fp32 C   MODE 1: gelu(acc+bias)->fp16   MODE 2: acc(+bias)+resid->fp32
// MODE 3: rope(acc) via table -> fp16 C16 (QKV)
// ---------------------------------------------------------------------------
template<int MODE>
__global__ __launch_bounds__(256)
void gemm_f16(const __half* __restrict__ A, const __half* __restrict__ B,
              const float* __restrict__ bias, const float* __restrict__ resid,
              float* __restrict__ C, __half* __restrict__ C16,
              const float2* __restrict__ tab, int N, int K)
{
    extern __shared__ __align__(128) char smem[];
    const uint32_t sb = s2u(smem);
    const int tid = threadIdx.x, warp = tid >> 5, lane = tid & 31;
    const int bm = blockIdx.y * 128, bn = blockIdx.x * 128;
    const int moff = (warp & 3) * 32, noff = (warp >> 2) * 64;
    const int g = lane >> 2, t = lane & 3;
    const int nk = K >> 5;
    const int lrow = tid >> 2, lc = tid & 3;

    float acc[2][8][4];
#pragma unroll
    for (int mi = 0; mi < 2; mi++)
#pragma unroll
        for (int ni = 0; ni < 8; ni++)
#pragma unroll
            for (int e = 0; e < 4; e++) acc[mi][ni][e] = 0.0f;

#define LOADST(st, ks) do { \
    const uint32_t so = sb + (uint32_t)(st) * 20480u; \
    const __half* gA = A + (size_t)(bm + lrow) * K + (ks) * 32 + lc * 8; \
    const __half* gB = B + (size_t)(bn + lrow) * K + (ks) * 32 + lc * 8; \
    const uint32_t sA = so + lrow * 80 + lc * 16; \
    const uint32_t sB = sA + 10240u; \
    cp16(sA, gA); cp16(sB, gB); \
    cp16(sA + 64 * 80, gA + (size_t)64 * K); \
    cp16(sB + 64 * 80, gB + (size_t)64 * K); \
} while (0)

    LOADST(0, 0);
    asm volatile("cp.async.commit_group;" ::: "memory");
    if (nk > 1) LOADST(1, 1);
    asm volatile("cp.async.commit_group;" ::: "memory");

    const uint32_t aoff = (uint32_t)((moff + (lane & 15)) * 80 + ((lane >> 4) & 1) * 16);
    const uint32_t boff = 10240u +
        (uint32_t)((noff + (lane & 7) + ((lane >> 4) & 1) * 8) * 80 + ((lane >> 3) & 1) * 16);

    for (int ks = 0; ks < nk; ks++) {
        asm volatile("cp.async.wait_group %0;" :: "n"(1) : "memory");
        __syncthreads();
        if (ks + 2 < nk) { LOADST((ks + 2) % 3, ks + 2); }
        asm volatile("cp.async.commit_group;" ::: "memory");

        const uint32_t so = sb + (uint32_t)(ks % 3) * 20480u;
#pragma unroll
        for (int kk = 0; kk < 2; kk++) {
            unsigned a0[4], a1[4], b[4][4];
            ldsm4(a0, so + aoff + kk * 32);
            ldsm4(a1, so + aoff + 16 * 80 + kk * 32);
#pragma unroll
            for (int nj = 0; nj < 4; nj++)
                ldsm4(b[nj], so + boff + nj * 16 * 80 + kk * 32);
#pragma unroll
            for (int nj = 0; nj < 4; nj++) {
                mma_f16(acc[0][2 * nj],     a0, &b[nj][0]);
                mma_f16(acc[0][2 * nj + 1], a0, &b[nj][2]);
                mma_f16(acc[1][2 * nj],     a1, &b[nj][0]);
                mma_f16(acc[1][2 * nj + 1], a1, &b[nj][2]);
            }
        }
    }
#undef LOADST

    if (MODE == 3) {
        const int region = (bn + noff) >> 10;
        if (region < 2) {
#pragma unroll
            for (int mi = 0; mi < 2; mi++) {
                const int r0 = bm + moff + 16 * mi + g;
                const int s0 = r0 & (SEQ - 1);
#pragma unroll
                for (int ni = 0; ni < 4; ni++) {
                    const int i0 = 8 * ni + 2 * t;
                    const float2 c00 = tab[s0 * 32 + i0];
                    const float2 c01 = tab[s0 * 32 + i0 + 1];
                    const float2 c10 = tab[(s0 + 8) * 32 + i0];
                    const float2 c11 = tab[(s0 + 8) * 32 + i0 + 1];
                    rot(acc[mi][ni][0], acc[mi][ni + 4][0], c00);
                    rot(acc[mi][ni][1], acc[mi][ni + 4][1], c01);
                    rot(acc[mi][ni][2], acc[mi][ni + 4][2], c10);
                    rot(acc[mi][ni][3], acc[mi][ni + 4][3], c11);
                }
            }
        }
    }

#pragma unroll
    for (int mi = 0; mi < 2; mi++) {
        const int r0 = bm + moff + 16 * mi + g;
#pragma unroll
        for (int ni = 0; ni < 8; ni++) {
            const int c = bn + noff + 8 * ni + 2 * t;
            float v00 = acc[mi][ni][0], v01 = acc[mi][ni][1];
            float v10 = acc[mi][ni][2], v11 = acc[mi][ni][3];
            if (MODE == 1 || MODE == 3) {
                if (MODE == 1) {
                    const float b0 = bias[c], b1 = bias[c + 1];
                    v00 = gelu_exact(v00 + b0); v01 = gelu_exact(v01 + b1);
                    v10 = gelu_exact(v10 + b0); v11 = gelu_exact(v11 + b1);
                }
                *(__half2*)(C16 + (size_t)r0 * N + c)       = __floats2half2_rn(v00, v01);
                *(__half2*)(C16 + (size_t)(r0 + 8) * N + c) = __floats2half2_rn(v10, v11);
            } else {
                if (MODE == 2) {
                    if (bias) {
                        const float b0 = bias[c], b1 = bias[c + 1];
                        v00 += b0; v01 += b1; v10 += b0; v11 += b1;
                    }
                    const float2 rr0 = *(const float2*)(resid + (size_t)r0 * N + c);
                    const float2 rr1 = *(const float2*)(resid + (size_t)(r0 + 8) * N + c);
                    v00 += rr0.x; v01 += rr0.y; v10 += rr1.x; v11 += rr1.y;
                }
                float2 o0; o0.x = v00; o0.y = v01;
                float2 o1; o1.x = v10; o1.y = v11;
                *(float2*)(C + (size_t)r0 * N + c) = o0;
                *(float2*)(C + (size_t)(r0 + 8) * N + c) = o1;
            }
        }
    }
}
#define GEMM_SMEM (3 * 20480)

// ---------------------------------------------------------------------------
// MMA flash attention v3: 128 queries/block, 8 warps, double-buffered K/V.
// grid (SEQ/128, NHEAD, BATCH), 256 threads, dynamic smem 90 KB.
// ---------------------------------------------------------------------------
#define ATTN_SMEM (128 * 144 + 4 * 64 * 144)   // Q + 2xK + 2xV = 55296+36864... (90KB)
__global__ __launch_bounds__(256, 2)
void attn_mma(const __half* __restrict__ U, __half* __restrict__ O)
{
    const int q0 = blockIdx.x * 128, h = blockIdx.y, b = blockIdx.z;
    const int tid = threadIdx.x, warp = tid >> 5, lane = tid & 31;
    const int g = lane >> 2, t = lane & 3;

    extern __shared__ __align__(128) char asm_[];
    const uint32_t qb = s2u(asm_);                 // Q: 128*144
    const uint32_t kb0 = qb + 128 * 144;           // K bufs: 2*64*144
    const uint32_t vb0 = kb0 + 2 * 64 * 144;       // V bufs: 2*64*144

    const __half* Ub = U + (size_t)(b * SEQ) * 3072 + h * 64;

    // load Q tile: 128 rows x 128B, 2 threads/row
    {
        const int r = tid >> 1;
        const int sg = (tid & 1) * 64;
        const __half* gq = Ub + (size_t)(q0 + r) * 3072 + sg / 2;
        const uint32_t sq = qb + r * 144 + sg;
        cp16(sq, gq); cp16(sq + 16, gq + 8);
        cp16(sq + 32, gq + 16); cp16(sq + 48, gq + 24);
    }
    asm volatile("cp.async.commit_group;" ::: "memory");
    asm volatile("cp.async.wait_group 0;" ::: "memory");
    __syncthreads();

    // Q fragments, pre-scaled by 0.125
    unsigned qf[4][4];
    {
        const uint32_t qa = qb + (16 * warp + (lane & 15)) * 144 + ((lane >> 4) & 1) * 16;
        const __half2 sc = __floats2half2_rn(0.125f, 0.125f);
#pragma unroll
        for (int kk = 0; kk < 4; kk++) {
            ldsm4(qf[kk], qa + kk * 32);
#pragma unroll
            for (int e = 0; e < 4; e++) {
                __half2 v = *(__half2*)&qf[kk][e];
                v = __hmul2(v, sc);
                qf[kk][e] = *(unsigned*)&v;
            }
        }
    }

    float o[8][4];
#pragma unroll
    for (int d = 0; d < 8; d++)
#pragma unroll
        for (int e = 0; e < 4; e++) o[d][e] = 0.0f;
    float m0 = -1e30f, m1 = -1e30f, l0 = 0.0f, l1 = 0.0f;
    const int wbase = q0 + 16 * warp;
    const int row0 = wbase + g;
    const int nch = (q0 >> 6) + 2;

#define LOADKV(ci) do { \
    const int _c0 = (ci) * 64; \
    const int _bf = (ci) & 1; \
    const int tt = tid & 127; \
    const int r = tt >> 1, sgh = (tt & 1) * 32; \
    const __half* gp = Ub + (size_t)(_c0 + r) * 3072 + ((tid >= 128) ? 2048 : 1024) + sgh; \
    const uint32_t sp = ((tid >= 128) ? vb0 : kb0) + _bf * (64 * 144) + r * 144 + sgh * 2; \
    cp16(sp, gp); cp16(sp + 16, gp + 8); \
    cp16(sp + 32, gp + 16); cp16(sp + 48, gp + 24); \
} while (0)

    LOADKV(0);
    asm volatile("cp.async.commit_group;" ::: "memory");

    for (int ci = 0; ci < nch; ci++) {
        const int c0 = ci * 64;
        const bool pre = (ci + 1 < nch);
        if (pre) {
            LOADKV(ci + 1);
            asm volatile("cp.async.commit_group;" ::: "memory");
            asm volatile("cp.async.wait_group 1;" ::: "memory");
        } else {
            asm volatile("cp.async.wait_group 0;" ::: "memory");
        }
        __syncthreads();

        const uint32_t kb = kb0 + (ci & 1) * (64 * 144);
        const uint32_t vb = vb0 + (ci & 1) * (64 * 144);

        float s[8][4];
#pragma unroll
        for (int j = 0; j < 8; j++)
#pragma unroll
            for (int e = 0; e < 4; e++) s[j][e] = 0.0f;
#pragma unroll
        for (int kk = 0; kk < 4; kk++) {
            unsigned bf[4][4];
#pragma unroll
            for (int nj = 0; nj < 4; nj++)
                ldsm4(bf[nj], kb + (nj * 16 + (lane & 7) + ((lane >> 4) & 1) * 8) * 144
                                + ((lane >> 3) & 1) * 16 + kk * 32);
#pragma unroll
            for (int nj = 0; nj < 4; nj++) {
                mma_f16(s[2 * nj],     qf[kk], &bf[nj][0]);
                mma_f16(s[2 * nj + 1], qf[kk], &bf[nj][2]);
            }
        }

        if (c0 + 63 > wbase) {          // chunk not fully visible to this warp
#pragma unroll
            for (int j = 0; j < 8; j++) {
                const int cb = c0 + 8 * j + 2 * t;
                if (cb     > row0)     s[j][0] = -1e30f;
                if (cb + 1 > row0)     s[j][1] = -1e30f;
                if (cb     > row0 + 8) s[j][2] = -1e30f;
                if (cb + 1 > row0 + 8) s[j][3] = -1e30f;
            }
        }

        float cm0 = -1e30f, cm1 = -1e30f;
#pragma unroll
        for (int j = 0; j < 8; j++) {
            cm0 = fmaxf(cm0, fmaxf(s[j][0], s[j][1]));
            cm1 = fmaxf(cm1, fmaxf(s[j][2], s[j][3]));
        }
        cm0 = fmaxf(cm0, __shfl_xor_sync(0xffffffff, cm0, 1));
        cm0 = fmaxf(cm0, __shfl_xor_sync(0xffffffff, cm0, 2));
        cm1 = fmaxf(cm1, __shfl_xor_sync(0xffffffff, cm1, 1));
        cm1 = fmaxf(cm1, __shfl_xor_sync(0xffffffff, cm1, 2));
        const float nm0 = fmaxf(m0, cm0), nm1 = fmaxf(m1, cm1);
        const float f0 = __expf(m0 - nm0), f1 = __expf(m1 - nm1);
        m0 = nm0; m1 = nm1;

        unsigned pf[4][4];
        float sum0 = 0.0f, sum1 = 0.0f;
#pragma unroll
        for (int nj = 0; nj < 4; nj++) {
            const float pa0 = __expf(s[2 * nj][0] - nm0), pa1 = __expf(s[2 * nj][1] - nm0);
            const float pa2 = __expf(s[2 * nj][2] - nm1), pa3 = __expf(s[2 * nj][3] - nm1);
            const float pb0 = __expf(s[2 * nj + 1][0] - nm0), pb1 = __expf(s[2 * nj + 1][1] - nm0);
            const float pb2 = __expf(s[2 * nj + 1][2] - nm1), pb3 = __expf(s[2 * nj + 1][3] - nm1);
            sum0 += pa0 + pa1 + pb0 + pb1;
            sum1 += pa2 + pa3 + pb2 + pb3;
            pf[nj][0] = packh2(pa0, pa1);
            pf[nj][1] = packh2(pa2, pa3);
            pf[nj][2] = packh2(pb0, pb1);
            pf[nj][3] = packh2(pb2, pb3);
        }
        sum0 += __shfl_xor_sync(0xffffffff, sum0, 1);
        sum0 += __shfl_xor_sync(0xffffffff, sum0, 2);
        sum1 += __shfl_xor_sync(0xffffffff, sum1, 1);
        sum1 += __shfl_xor_sync(0xffffffff, sum1, 2);
        l0 = l0 * f0 + sum0;
        l1 = l1 * f1 + sum1;

#pragma unroll
        for (int d = 0; d < 8; d++) {
            o[d][0] *= f0; o[d][1] *= f0; o[d][2] *= f1; o[d][3] *= f1;
        }

#pragma unroll
        for (int kk = 0; kk < 4; kk++) {
            unsigned vf[4][4];
#pragma unroll
            for (int dj = 0; dj < 4; dj++)
                ldsm4t(vf[dj], vb + (kk * 16 + (lane & 7) + ((lane >> 3) & 1) * 8) * 144
                                 + (dj * 16 + ((lane >> 4) & 1) * 8) * 2);
#pragma unroll
            for (int dj = 0; dj < 4; dj++) {
                mma_f16(o[2 * dj],     pf[kk], &vf[dj][0]);
                mma_f16(o[2 * dj + 1], pf[kk], &vf[dj][2]);
            }
        }
        __syncthreads();
    }
#undef LOADKV

    const float il0 = 1.0f / l0, il1 = 1.0f / l1;
    __half* Ob = O + (size_t)(b * SEQ + row0) * TDIM + h * 64;
#pragma unroll
    for (int dj = 0; dj < 8; dj++) {
        const int c = 8 * dj + 2 * t;
        *(__half2*)(Ob + c)            = __floats2half2_rn(o[dj][0] * il0, o[dj][1] * il0);
        *(__half2*)(Ob + 8 * TDIM + c) = __floats2half2_rn(o[dj][2] * il1, o[dj][3] * il1);
    }
}

// ---------------------------------------------------------------------------
__global__ void conv16(const float* __restrict__ s, __half* __restrict__ d, int n4)
{
    for (int i = blockIdx.x * blockDim.x + threadIdx.x; i < n4; i += gridDim.x * blockDim.x) {
        const float4 v = ((const float4*)s)[i];
        ((__half2*)d)[2 * i]     = __floats2half2_rn(v.x, v.y);
        ((__half2*)d)[2 * i + 1] = __floats2half2_rn(v.z, v.w);
    }
}

__global__ void prep_kernel(const int* __restrict__ ids, const float* __restrict__ emb,
                            float* __restrict__ x, float2* __restrict__ tab,
                            const float* __restrict__ Wu, __half* __restrict__ wu16)
{
    if (blockIdx.x < NROWS) {
        ((float4*)(x + (size_t)blockIdx.x * DMODEL))[threadIdx.x] =
            ((const float4*)(emb + (size_t)ids[blockIdx.x] * DMODEL))[threadIdx.x];
    } else if (blockIdx.x < NROWS + 128) {
        const int idx = (blockIdx.x - NROWS) * 256 + threadIdx.x;
        const int s = idx >> 5, i = idx & 31;
        const float inv = exp2f(-(float)(2 * i) * (1.0f / 64.0f) * 13.287712379549449f);
        float sn, cs;
        sincosf((float)s * inv, &sn, &cs);
        tab[idx] = make_float2(cs, sn);
    } else {
        const int n4 = NLAYER * 3 * TDIM * DMODEL / 4;
        for (int i = (blockIdx.x - NROWS - 128) * 256 + threadIdx.x; i < n4; i += 2048 * 256) {
            const float4 v = ((const float4*)Wu)[i];
            ((__half2*)wu16)[2 * i]     = __floats2half2_rn(v.x, v.y);
            ((__half2*)wu16)[2 * i + 1] = __floats2half2_rn(v.z, v.w);
        }
    }
}

__global__ __launch_bounds__(256)
void layernorm_kernel(const float* __restrict__ x, const float* __restrict__ w,
                      const float* __restrict__ b, __half* __restrict__ y16)
{
    const int row = blockIdx.x, tid = threadIdx.x;
    __shared__ float red[256];

    const float4 v = ((const float4*)(x + (size_t)row * DMODEL))[tid];
    red[tid] = v.x + v.y + v.z + v.w; __syncthreads();
    for (int k = 128; k > 0; k >>= 1) { if (tid < k) red[tid] += red[tid + k]; __syncthreads(); }
    const float mu = red[0] * (1.0f / DMODEL); __syncthreads();

    const float dx = v.x - mu, dy = v.y - mu, dz = v.z - mu, dw = v.w - mu;
    red[tid] = dx * dx + dy * dy + dz * dz + dw * dw; __syncthreads();
    for (int k = 128; k > 0; k >>= 1) { if (tid < k) red[tid] += red[tid + k]; __syncthreads(); }
    const float rs = rsqrtf(red[0] * (1.0f / DMODEL) + 1e-5f);

    const float4 wv = ((const float4*)w)[tid];
    const float4 bv = ((const float4*)b)[tid];
    const __half2 h0 = __floats2half2_rn(dx * rs * wv.x + bv.x, dy * rs * wv.y + bv.y);
    const __half2 h1 = __floats2half2_rn(dz * rs * wv.z + bv.z, dw * rs * wv.w + bv.w);
    uint2 out; out.x = *(const unsigned*)&h0; out.y = *(const unsigned*)&h1;
    ((uint2*)(y16 + (size_t)row * DMODEL))[tid] = out;
}

extern "C" void kernel_launch(void* const* d_in, const int* in_sizes, int n_in,
                              void* d_out, int out_size)
{
    (void)in_sizes; (void)n_in; (void)out_size;

    const int*   ids = (const int*)  d_in[0];
    const float* emb = (const float*)d_in[1];
    const float* Wu  = (const float*)d_in[2];
    const float* Wo  = (const float*)d_in[3];
    const float* n1w = (const float*)d_in[4];
    const float* n1b = (const float*)d_in[5];
    const float* n2w = (const float*)d_in[6];
    const float* n2b = (const float*)d_in[7];
    const float* f1w = (const float*)d_in[8];
    const float* f1b = (const float*)d_in[9];
    const float* f2w = (const float*)d_in[10];
    const float* f2b = (const float*)d_in[11];
    const float* fnw = (const float*)d_in[12];
    const float* fnb = (const float*)d_in[13];
    float* out = (float*)d_out;

    float *x; float2* tab; __half *u16, *xn16, *at16, *h16, *w16;
    cudaGetSymbolAddress((void**)&x,    g_x);
    cudaGetSymbolAddress((void**)&tab,  g_rope);
    cudaGetSymbolAddress((void**)&u16,  g_u16);
    cudaGetSymbolAddress((void**)&xn16, g_xn16);
    cudaGetSymbolAddress((void**)&at16, g_at16);
    cudaGetSymbolAddress((void**)&h16,  g_h16);
    cudaGetSymbolAddress((void**)&w16,  g_w16);

    cudaFuncSetAttribute(gemm_f16<0>, cudaFuncAttributeMaxDynamicSharedMemorySize, GEMM_SMEM);
    cudaFuncSetAttribute(gemm_f16<1>, cudaFuncAttributeMaxDynamicSharedMemorySize, GEMM_SMEM);
    cudaFuncSetAttribute(gemm_f16<2>, cudaFuncAttributeMaxDynamicSharedMemorySize, GEMM_SMEM);
    cudaFuncSetAttribute(gemm_f16<3>, cudaFuncAttributeMaxDynamicSharedMemorySize, GEMM_SMEM);
    cudaFuncSetAttribute(attn_mma,    cudaFuncAttributeMaxDynamicSharedMemorySize, ATTN_SMEM);

    // 1: prep   2: LN   3: QKV   4: attn (ncu anchor)
    prep_kernel<<<NROWS + 128 + 2048, 256>>>(ids, emb, x, tab, Wu, w16 + WU16);
    layernorm_kernel<<<NROWS, 256>>>(x, n1w, n1b, xn16);
    gemm_f16<3><<<dim3(3 * TDIM / 128, NROWS / 128), 256, GEMM_SMEM>>>(
        xn16, w16 + WU16, nullptr, nullptr, nullptr, u16, tab, 3 * TDIM, DMODEL);
    attn_mma<<<dim3(SEQ / 128, NHEAD, BATCH), 256, ATTN_SMEM>>>(u16, at16);

    conv16<<<2048, 256>>>(Wo,  w16 + WO16,  NLAYER * DMODEL * TDIM / 4);
    conv16<<<2048, 256>>>(f1w, w16 + F116,  NLAYER * FFDIM * DMODEL / 4);
    conv16<<<2048, 256>>>(f2w, w16 + F216,  NLAYER * DMODEL * FFDIM / 4);
    conv16<<<2048, 256>>>(emb, w16 + EMB16, VOCAB * DMODEL / 4);

    for (int l = 0; l < NLAYER; l++) {
        const __half* Wu_l = w16 + WU16 + (size_t)l * 3 * TDIM * DMODEL;
        const __half* Wo_l = w16 + WO16 + (size_t)l * DMODEL * TDIM;
        const __half* f1_l = w16 + F116 + (size_t)l * FFDIM * DMODEL;
        const __half* f2_l = w16 + F216 + (size_t)l * DMODEL * FFDIM;

        if (l > 0) {
            layernorm_kernel<<<NROWS, 256>>>(x, n1w + l * DMODEL, n1b + l * DMODEL, xn16);
            gemm_f16<3><<<dim3(3 * TDIM / 128, NROWS / 128), 256, GEMM_SMEM>>>(
                xn16, Wu_l, nullptr, nullptr, nullptr, u16, tab, 3 * TDIM, DMODEL);
            attn_mma<<<dim3(SEQ / 128, NHEAD, BATCH), 256, ATTN_SMEM>>>(u16, at16);
        }

        gemm_f16<2><<<dim3(DMODEL / 128, NROWS / 128), 256, GEMM_SMEM>>>(
            at16, Wo_l, nullptr, x, x, nullptr, nullptr, DMODEL, TDIM);

        layernorm_kernel<<<NROWS, 256>>>(x, n2w + l * DMODEL, n2b + l * DMODEL, xn16);

        gemm_f16<1><<<dim3(FFDIM / 128, NROWS / 128), 256, GEMM_SMEM>>>(
            xn16, f1_l, f1b + (size_t)l * FFDIM, nullptr, nullptr, h16, nullptr, FFDIM, DMODEL);

        gemm_f16<2><<<dim3(DMODEL / 128, NROWS / 128), 256, GEMM_SMEM>>>(
            h16, f2_l, f2b + (size_t)l * DMODEL, x, x, nullptr, nullptr, DMODEL, FFDIM);
    }

    layernorm_kernel<<<NROWS, 256>>>(x, fnw, fnb, xn16);

    gemm_f16<0><<<dim3(VOCAB / 128, NROWS / 128), 256, GEMM_SMEM>>>(
        xn16, w16 + EMB16, nullptr, nullptr, out, nullptr, nullptr, VOCAB, DMODEL);
}

// round 11
// speedup vs baseline: 2.5841x; 1.0185x over previous
#include <cuda_runtime.h>
#include <cuda_fp16.h>
#include <math.h>
#include <stdint.h>

#define BATCH   2
#define SEQ     1024
#define NROWS   (BATCH * SEQ)
#define DMODEL  1024
#define NHEAD   16
#define HDIM    64
#define TDIM    1024
#define FFDIM   4096
#define NLAYER  8
#define VOCAB   32000

#define WU16  0
#define WO16  25165824u
#define F116  33554432u
#define F216  67108864u
#define EMB16 100663296u
#define W16_TOTAL 133431296u

__device__ float  g_x [NROWS * DMODEL];
__device__ float2 g_rope[SEQ * 32];
__device__ __half g_u16 [NROWS * 3 * TDIM];
__device__ __half g_xn16[NROWS * DMODEL];
__device__ __half g_at16[NROWS * TDIM];
__device__ __half g_h16 [NROWS * FFDIM];
__device__ __half g_w16 [W16_TOTAL];

__device__ __forceinline__ float gelu_exact(float v) {
    return 0.5f * v * (1.0f + erff(v * 0.70710678118654752440f));
}
__device__ __forceinline__ uint32_t s2u(const void* p) {
    uint32_t a;
    asm("{ .reg .u64 t; cvta.to.shared.u64 t, %1; cvt.u32.u64 %0, t; }" : "=r"(a) : "l"(p));
    return a;
}
__device__ __forceinline__ void cp16(uint32_t s, const void* g) {
    asm volatile("cp.async.cg.shared.global [%0], [%1], 16;" :: "r"(s), "l"(g));
}
__device__ __forceinline__ void ldsm4(unsigned* r, uint32_t a) {
    asm volatile("ldmatrix.sync.aligned.m8n8.x4.shared.b16 {%0,%1,%2,%3}, [%4];"
        : "=r"(r[0]), "=r"(r[1]), "=r"(r[2]), "=r"(r[3]) : "r"(a));
}
__device__ __forceinline__ void ldsm4t(unsigned* r, uint32_t a) {
    asm volatile("ldmatrix.sync.aligned.m8n8.x4.trans.shared.b16 {%0,%1,%2,%3}, [%4];"
        : "=r"(r[0]), "=r"(r[1]), "=r"(r[2]), "=r"(r[3]) : "r"(a));
}
__device__ __forceinline__ void mma_f16(float* c, const unsigned* a, const unsigned* b) {
    asm volatile(
        "mma.sync.aligned.m16n8k16.row.col.f32.f16.f16.f32 "
        "{%0,%1,%2,%3},{%4,%5,%6,%7},{%8,%9},{%0,%1,%2,%3};"
        : "+f"(c[0]), "+f"(c[1]), "+f"(c[2]), "+f"(c[3])
        : "r"(a[0]), "r"(a[1]), "r"(a[2]), "r"(a[3]), "r"(b[0]), "r"(b[1]));
}
__device__ __forceinline__ void rot(float& a, float& b, float2 cs) {
    const float t0 = a * cs.x - b * cs.y;
    b = b * cs.x + a * cs.y;
    a = t0;
}
__device__ __forceinline__ unsigned packh2(float a, float b) {
    __half2 h = __floats2half2_rn(a, b);
    return *(unsigned*)&h;
}

// ---------------------------------------------------------------------------
// fp16 GEMM (proven config): C = A @ B^T
// MODE 0: fp32 C   MODE 1: gelu(acc+bias)->fp16   MODE 2: acc(+bias)+resid->fp32
// MODE 3: rope(acc) via table -> fp16 C16 (QKV)
// ---------------------------------------------------------------------------
template<int MODE>
__global__ __launch_bounds__(256)
void gemm_f16(const __half* __restrict__ A, const __half* __restrict__ B,
              const float* __restrict__ bias, const float* __restrict__ resid,
              float* __restrict__ C, __half* __restrict__ C16,
              const float2* __restrict__ tab, int N, int K)
{
    extern __shared__ __align__(128) char smem[];
    const uint32_t sb = s2u(smem);
    const int tid = threadIdx.x, warp = tid >> 5, lane = tid & 31;
    const int bm = blockIdx.y * 128, bn = blockIdx.x * 128;
    const int moff = (warp & 3) * 32, noff = (warp >> 2) * 64;
    const int g = lane >> 2, t = lane & 3;
    const int nk = K >> 5;
    const int lrow = tid >> 2, lc = tid & 3;

    float acc[2][8][4];
#pragma unroll
    for (int mi = 0; mi < 2; mi++)
#pragma unroll
        for (int ni = 0; ni < 8; ni++)
#pragma unroll
            for (int e = 0; e < 4; e++) acc[mi][ni][e] = 0.0f;

#define LOADST(st, ks) do { \
    const uint32_t so = sb + (uint32_t)(st) * 20480u; \
    const __half* gA = A + (size_t)(bm + lrow) * K + (ks) * 32 + lc * 8; \
    const __half* gB = B + (size_t)(bn + lrow) * K + (ks) * 32 + lc * 8; \
    const uint32_t sA = so + lrow * 80 + lc * 16; \
    const uint32_t sB = sA + 10240u; \
    cp16(sA, gA); cp16(sB, gB); \
    cp16(sA + 64 * 80, gA + (size_t)64 * K); \
    cp16(sB + 64 * 80, gB + (size_t)64 * K); \
} while (0)

    LOADST(0, 0);
    asm volatile("cp.async.commit_group;" ::: "memory");
    if (nk > 1) LOADST(1, 1);
    asm volatile("cp.async.commit_group;" ::: "memory");

    const uint32_t aoff = (uint32_t)((moff + (lane & 15)) * 80 + ((lane >> 4) & 1) * 16);
    const uint32_t boff = 10240u +
        (uint32_t)((noff + (lane & 7) + ((lane >> 4) & 1) * 8) * 80 + ((lane >> 3) & 1) * 16);

    for (int ks = 0; ks < nk; ks++) {
        asm volatile("cp.async.wait_group %0;" :: "n"(1) : "memory");
        __syncthreads();
        if (ks + 2 < nk) { LOADST((ks + 2) % 3, ks + 2); }
        asm volatile("cp.async.commit_group;" ::: "memory");

        const uint32_t so = sb + (uint32_t)(ks % 3) * 20480u;
#pragma unroll
        for (int kk = 0; kk < 2; kk++) {
            unsigned a0[4], a1[4], b[4][4];
            ldsm4(a0, so + aoff + kk * 32);
            ldsm4(a1, so + aoff + 16 * 80 + kk * 32);
#pragma unroll
            for (int nj = 0; nj < 4; nj++)
                ldsm4(b[nj], so + boff + nj * 16 * 80 + kk * 32);
#pragma unroll
            for (int nj = 0; nj < 4; nj++) {
                mma_f16(acc[0][2 * nj],     a0, &b[nj][0]);
                mma_f16(acc[0][2 * nj + 1], a0, &b[nj][2]);
                mma_f16(acc[1][2 * nj],     a1, &b[nj][0]);
                mma_f16(acc[1][2 * nj + 1], a1, &b[nj][2]);
            }
        }
    }
#undef LOADST

    if (MODE == 3) {
        const int region = (bn + noff) >> 10;
        if (region < 2) {
#pragma unroll
            for (int mi = 0; mi < 2; mi++) {
                const int r0 = bm + moff + 16 * mi + g;
                const int s0 = r0 & (SEQ - 1);
#pragma unroll
                for (int ni = 0; ni < 4; ni++) {
                    const int i0 = 8 * ni + 2 * t;
                    const float2 c00 = tab[s0 * 32 + i0];
                    const float2 c01 = tab[s0 * 32 + i0 + 1];
                    const float2 c10 = tab[(s0 + 8) * 32 + i0];
                    const float2 c11 = tab[(s0 + 8) * 32 + i0 + 1];
                    rot(acc[mi][ni][0], acc[mi][ni + 4][0], c00);
                    rot(acc[mi][ni][1], acc[mi][ni + 4][1], c01);
                    rot(acc[mi][ni][2], acc[mi][ni + 4][2], c10);
                    rot(acc[mi][ni][3], acc[mi][ni + 4][3], c11);
                }
            }
        }
    }

#pragma unroll
    for (int mi = 0; mi < 2; mi++) {
        const int r0 = bm + moff + 16 * mi + g;
#pragma unroll
        for (int ni = 0; ni < 8; ni++) {
            const int c = bn + noff + 8 * ni + 2 * t;
            float v00 = acc[mi][ni][0], v01 = acc[mi][ni][1];
            float v10 = acc[mi][ni][2], v11 = acc[mi][ni][3];
            if (MODE == 1 || MODE == 3) {
                if (MODE == 1) {
                    const float b0 = bias[c], b1 = bias[c + 1];
                    v00 = gelu_exact(v00 + b0); v01 = gelu_exact(v01 + b1);
                    v10 = gelu_exact(v10 + b0); v11 = gelu_exact(v11 + b1);
                }
                *(__half2*)(C16 + (size_t)r0 * N + c)       = __floats2half2_rn(v00, v01);
                *(__half2*)(C16 + (size_t)(r0 + 8) * N + c) = __floats2half2_rn(v10, v11);
            } else {
                if (MODE == 2) {
                    if (bias) {
                        const float b0 = bias[c], b1 = bias[c + 1];
                        v00 += b0; v01 += b1; v10 += b0; v11 += b1;
                    }
                    const float2 rr0 = *(const float2*)(resid + (size_t)r0 * N + c);
                    const float2 rr1 = *(const float2*)(resid + (size_t)(r0 + 8) * N + c);
                    v00 += rr0.x; v01 += rr0.y; v10 += rr1.x; v11 += rr1.y;
                }
                float2 o0; o0.x = v00; o0.y = v01;
                float2 o1; o1.x = v10; o1.y = v11;
                *(float2*)(C + (size_t)r0 * N + c) = o0;
                *(float2*)(C + (size_t)(r0 + 8) * N + c) = o1;
            }
        }
    }
}
#define GEMM_SMEM (3 * 20480)

// ---------------------------------------------------------------------------
// MMA flash attention v3 (unchanged from R10)
// ---------------------------------------------------------------------------
#define ATTN_SMEM (128 * 144 + 4 * 64 * 144)
__global__ __launch_bounds__(256, 2)
void attn_mma(const __half* __restrict__ U, __half* __restrict__ O)
{
    const int q0 = blockIdx.x * 128, h = blockIdx.y, b = blockIdx.z;
    const int tid = threadIdx.x, warp = tid >> 5, lane = tid & 31;
    const int g = lane >> 2, t = lane & 3;

    extern __shared__ __align__(128) char asm_[];
    const uint32_t qb = s2u(asm_);
    const uint32_t kb0 = qb + 128 * 144;
    const uint32_t vb0 = kb0 + 2 * 64 * 144;

    const __half* Ub = U + (size_t)(b * SEQ) * 3072 + h * 64;

    {
        const int r = tid >> 1;
        const int sg = (tid & 1) * 64;
        const __half* gq = Ub + (size_t)(q0 + r) * 3072 + sg / 2;
        const uint32_t sq = qb + r * 144 + sg;
        cp16(sq, gq); cp16(sq + 16, gq + 8);
        cp16(sq + 32, gq + 16); cp16(sq + 48, gq + 24);
    }
    asm volatile("cp.async.commit_group;" ::: "memory");
    asm volatile("cp.async.wait_group 0;" ::: "memory");
    __syncthreads();

    unsigned qf[4][4];
    {
        const uint32_t qa = qb + (16 * warp + (lane & 15)) * 144 + ((lane >> 4) & 1) * 16;
        const __half2 sc = __floats2half2_rn(0.125f, 0.125f);
#pragma unroll
        for (int kk = 0; kk < 4; kk++) {
            ldsm4(qf[kk], qa + kk * 32);
#pragma unroll
            for (int e = 0; e < 4; e++) {
                __half2 v = *(__half2*)&qf[kk][e];
                v = __hmul2(v, sc);
                qf[kk][e] = *(unsigned*)&v;
            }
        }
    }

    float o[8][4];
#pragma unroll
    for (int d = 0; d < 8; d++)
#pragma unroll
        for (int e = 0; e < 4; e++) o[d][e] = 0.0f;
    float m0 = -1e30f, m1 = -1e30f, l0 = 0.0f, l1 = 0.0f;
    const int wbase = q0 + 16 * warp;
    const int row0 = wbase + g;
    const int nch = (q0 >> 6) + 2;

#define LOADKV(ci) do { \
    const int _c0 = (ci) * 64; \
    const int _bf = (ci) & 1; \
    const int tt = tid & 127; \
    const int r = tt >> 1, sgh = (tt & 1) * 32; \
    const __half* gp = Ub + (size_t)(_c0 + r) * 3072 + ((tid >= 128) ? 2048 : 1024) + sgh; \
    const uint32_t sp = ((tid >= 128) ? vb0 : kb0) + _bf * (64 * 144) + r * 144 + sgh * 2; \
    cp16(sp, gp); cp16(sp + 16, gp + 8); \
    cp16(sp + 32, gp + 16); cp16(sp + 48, gp + 24); \
} while (0)

    LOADKV(0);
    asm volatile("cp.async.commit_group;" ::: "memory");

    for (int ci = 0; ci < nch; ci++) {
        const int c0 = ci * 64;
        const bool pre = (ci + 1 < nch);
        if (pre) {
            LOADKV(ci + 1);
            asm volatile("cp.async.commit_group;" ::: "memory");
            asm volatile("cp.async.wait_group 1;" ::: "memory");
        } else {
            asm volatile("cp.async.wait_group 0;" ::: "memory");
        }
        __syncthreads();

        const uint32_t kb = kb0 + (ci & 1) * (64 * 144);
        const uint32_t vb = vb0 + (ci & 1) * (64 * 144);

        float s[8][4];
#pragma unroll
        for (int j = 0; j < 8; j++)
#pragma unroll
            for (int e = 0; e < 4; e++) s[j][e] = 0.0f;
#pragma unroll
        for (int kk = 0; kk < 4; kk++) {
            unsigned bf[4][4];
#pragma unroll
            for (int nj = 0; nj < 4; nj++)
                ldsm4(bf[nj], kb + (nj * 16 + (lane & 7) + ((lane >> 4) & 1) * 8) * 144
                                + ((lane >> 3) & 1) * 16 + kk * 32);
#pragma unroll
            for (int nj = 0; nj < 4; nj++) {
                mma_f16(s[2 * nj],     qf[kk], &bf[nj][0]);
                mma_f16(s[2 * nj + 1], qf[kk], &bf[nj][2]);
            }
        }

        if (c0 + 63 > wbase) {
#pragma unroll
            for (int j = 0; j < 8; j++) {
                const int cb = c0 + 8 * j + 2 * t;
                if (cb     > row0)     s[j][0] = -1e30f;
                if (cb + 1 > row0)     s[j][1] = -1e30f;
                if (cb     > row0 + 8) s[j][2] = -1e30f;
                if (cb + 1 > row0 + 8) s[j][3] = -1e30f;
            }
        }

        float cm0 = -1e30f, cm1 = -1e30f;
#pragma unroll
        for (int j = 0; j < 8; j++) {
            cm0 = fmaxf(cm0, fmaxf(s[j][0], s[j][1]));
            cm1 = fmaxf(cm1, fmaxf(s[j][2], s[j][3]));
        }
        cm0 = fmaxf(cm0, __shfl_xor_sync(0xffffffff, cm0, 1));
        cm0 = fmaxf(cm0, __shfl_xor_sync(0xffffffff, cm0, 2));
        cm1 = fmaxf(cm1, __shfl_xor_sync(0xffffffff, cm1, 1));
        cm1 = fmaxf(cm1, __shfl_xor_sync(0xffffffff, cm1, 2));
        const float nm0 = fmaxf(m0, cm0), nm1 = fmaxf(m1, cm1);
        const float f0 = __expf(m0 - nm0), f1 = __expf(m1 - nm1);
        m0 = nm0; m1 = nm1;

        unsigned pf[4][4];
        float sum0 = 0.0f, sum1 = 0.0f;
#pragma unroll
        for (int nj = 0; nj < 4; nj++) {
            const float pa0 = __expf(s[2 * nj][0] - nm0), pa1 = __expf(s[2 * nj][1] - nm0);
            const float pa2 = __expf(s[2 * nj][2] - nm1), pa3 = __expf(s[2 * nj][3] - nm1);
            const float pb0 = __expf(s[2 * nj + 1][0] - nm0), pb1 = __expf(s[2 * nj + 1][1] - nm0);
            const float pb2 = __expf(s[2 * nj + 1][2] - nm1), pb3 = __expf(s[2 * nj + 1][3] - nm1);
            sum0 += pa0 + pa1 + pb0 + pb1;
            sum1 += pa2 + pa3 + pb2 + pb3;
            pf[nj][0] = packh2(pa0, pa1);
            pf[nj][1] = packh2(pa2, pa3);
            pf[nj][2] = packh2(pb0, pb1);
            pf[nj][3] = packh2(pb2, pb3);
        }
        sum0 += __shfl_xor_sync(0xffffffff, sum0, 1);
        sum0 += __shfl_xor_sync(0xffffffff, sum0, 2);
        sum1 += __shfl_xor_sync(0xffffffff, sum1, 1);
        sum1 += __shfl_xor_sync(0xffffffff, sum1, 2);
        l0 = l0 * f0 + sum0;
        l1 = l1 * f1 + sum1;

#pragma unroll
        for (int d = 0; d < 8; d++) {
            o[d][0] *= f0; o[d][1] *= f0; o[d][2] *= f1; o[d][3] *= f1;
        }

#pragma unroll
        for (int kk = 0; kk < 4; kk++) {
            unsigned vf[4][4];
#pragma unroll
            for (int dj = 0; dj < 4; dj++)
                ldsm4t(vf[dj], vb + (kk * 16 + (lane & 7) + ((lane >> 3) & 1) * 8) * 144
                                 + (dj * 16 + ((lane >> 4) & 1) * 8) * 2);
#pragma unroll
            for (int dj = 0; dj < 4; dj++) {
                mma_f16(o[2 * dj],     pf[kk], &vf[dj][0]);
                mma_f16(o[2 * dj + 1], pf[kk], &vf[dj][2]);
            }
        }
        __syncthreads();
    }
#undef LOADKV

    const float il0 = 1.0f / l0, il1 = 1.0f / l1;
    __half* Ob = O + (size_t)(b * SEQ + row0) * TDIM + h * 64;
#pragma unroll
    for (int dj = 0; dj < 8; dj++) {
        const int c = 8 * dj + 2 * t;
        *(__half2*)(Ob + c)            = __floats2half2_rn(o[dj][0] * il0, o[dj][1] * il0);
        *(__half2*)(Ob + 8 * TDIM + c) = __floats2half2_rn(o[dj][2] * il1, o[dj][3] * il1);
    }
}

// ---------------------------------------------------------------------------
__global__ void conv16(const float* __restrict__ s, __half* __restrict__ d, int n4)
{
    for (int i = blockIdx.x * blockDim.x + threadIdx.x; i < n4; i += gridDim.x * blockDim.x) {
        const float4 v = ((const float4*)s)[i];
        ((__half2*)d)[2 * i]     = __floats2half2_rn(v.x, v.y);
        ((__half2*)d)[2 * i + 1] = __floats2half2_rn(v.z, v.w);
    }
}

__global__ void prep_kernel(const int* __restrict__ ids, const float* __restrict__ emb,
                            float* __restrict__ x, float2* __restrict__ tab,
                            const float* __restrict__ Wu, __half* __restrict__ wu16)
{
    if (blockIdx.x < NROWS) {
        ((float4*)(x + (size_t)blockIdx.x * DMODEL))[threadIdx.x] =
            ((const float4*)(emb + (size_t)ids[blockIdx.x] * DMODEL))[threadIdx.x];
    } else if (blockIdx.x < NROWS + 128) {
        const int idx = (blockIdx.x - NROWS) * 256 + threadIdx.x;
        const int s = idx >> 5, i = idx & 31;
        const float inv = exp2f(-(float)(2 * i) * (1.0f / 64.0f) * 13.287712379549449f);
        float sn, cs;
        sincosf((float)s * inv, &sn, &cs);
        tab[idx] = make_float2(cs, sn);
    } else {
        const int n4 = NLAYER * 3 * TDIM * DMODEL / 4;
        for (int i = (blockIdx.x - NROWS - 128) * 256 + threadIdx.x; i < n4; i += 2048 * 256) {
            const float4 v = ((const float4*)Wu)[i];
            ((__half2*)wu16)[2 * i]     = __floats2half2_rn(v.x, v.y);
            ((__half2*)wu16)[2 * i + 1] = __floats2half2_rn(v.z, v.w);
        }
    }
}

// warp-per-row LayerNorm -> fp16 (shfl reductions, no block barriers)
__global__ __launch_bounds__(256)
void layernorm_kernel(const float* __restrict__ x, const float* __restrict__ w,
                      const float* __restrict__ b, __half* __restrict__ y16)
{
    const int warp = threadIdx.x >> 5, lane = threadIdx.x & 31;
    const int row = blockIdx.x * 8 + warp;
    const float4* xr = (const float4*)(x + (size_t)row * DMODEL);

    float4 v[8];
    float s = 0.0f;
#pragma unroll
    for (int j = 0; j < 8; j++) {
        v[j] = xr[lane + 32 * j];
        s += v[j].x + v[j].y + v[j].z + v[j].w;
    }
#pragma unroll
    for (int o = 16; o > 0; o >>= 1) s += __shfl_xor_sync(0xffffffff, s, o);
    const float mu = s * (1.0f / DMODEL);

    float q = 0.0f;
#pragma unroll
    for (int j = 0; j < 8; j++) {
        const float a = v[j].x - mu, b2 = v[j].y - mu, c = v[j].z - mu, d = v[j].w - mu;
        q += a * a + b2 * b2 + c * c + d * d;
    }
#pragma unroll
    for (int o = 16; o > 0; o >>= 1) q += __shfl_xor_sync(0xffffffff, q, o);
    const float rs = rsqrtf(q * (1.0f / DMODEL) + 1e-5f);

    uint2* yr = (uint2*)(y16 + (size_t)row * DMODEL);
#pragma unroll
    for (int j = 0; j < 8; j++) {
        const int idx = lane + 32 * j;
        const float4 wv = ((const float4*)w)[idx];
        const float4 bv = ((const float4*)b)[idx];
        const __half2 h0 = __floats2half2_rn((v[j].x - mu) * rs * wv.x + bv.x,
                                             (v[j].y - mu) * rs * wv.y + bv.y);
        const __half2 h1 = __floats2half2_rn((v[j].z - mu) * rs * wv.z + bv.z,
                                             (v[j].w - mu) * rs * wv.w + bv.w);
        uint2 o; o.x = *(const unsigned*)&h0; o.y = *(const unsigned*)&h1;
        yr[idx] = o;
    }
}

extern "C" void kernel_launch(void* const* d_in, const int* in_sizes, int n_in,
                              void* d_out, int out_size)
{
    (void)in_sizes; (void)n_in; (void)out_size;

    const int*   ids = (const int*)  d_in[0];
    const float* emb = (const float*)d_in[1];
    const float* Wu  = (const float*)d_in[2];
    const float* Wo  = (const float*)d_in[3];
    const float* n1w = (const float*)d_in[4];
    const float* n1b = (const float*)d_in[5];
    const float* n2w = (const float*)d_in[6];
    const float* n2b = (const float*)d_in[7];
    const float* f1w = (const float*)d_in[8];
    const float* f1b = (const float*)d_in[9];
    const float* f2w = (const float*)d_in[10];
    const float* f2b = (const float*)d_in[11];
    const float* fnw = (const float*)d_in[12];
    const float* fnb = (const float*)d_in[13];
    float* out = (float*)d_out;

    float *x; float2* tab; __half *u16, *xn16, *at16, *h16, *w16;
    cudaGetSymbolAddress((void**)&x,    g_x);
    cudaGetSymbolAddress((void**)&tab,  g_rope);
    cudaGetSymbolAddress((void**)&u16,  g_u16);
    cudaGetSymbolAddress((void**)&xn16, g_xn16);
    cudaGetSymbolAddress((void**)&at16, g_at16);
    cudaGetSymbolAddress((void**)&h16,  g_h16);
    cudaGetSymbolAddress((void**)&w16,  g_w16);

    cudaFuncSetAttribute(gemm_f16<0>, cudaFuncAttributeMaxDynamicSharedMemorySize, GEMM_SMEM);
    cudaFuncSetAttribute(gemm_f16<1>, cudaFuncAttributeMaxDynamicSharedMemorySize, GEMM_SMEM);
    cudaFuncSetAttribute(gemm_f16<2>, cudaFuncAttributeMaxDynamicSharedMemorySize, GEMM_SMEM);
    cudaFuncSetAttribute(gemm_f16<3>, cudaFuncAttributeMaxDynamicSharedMemorySize, GEMM_SMEM);
    cudaFuncSetAttribute(attn_mma,    cudaFuncAttributeMaxDynamicSharedMemorySize, ATTN_SMEM);

    static cudaStream_t s2 = nullptr;
    static cudaEvent_t evF = nullptr, evD = nullptr;
    if (!s2) {
        cudaStreamCreateWithFlags(&s2, cudaStreamNonBlocking);
        cudaEventCreateWithFlags(&evF, cudaEventDisableTiming);
        cudaEventCreateWithFlags(&evD, cudaEventDisableTiming);
    }

    // 1: prep   2: LN   3: conv emb   4: QKV GEMM (ncu anchor)
    prep_kernel<<<NROWS + 128 + 2048, 256>>>(ids, emb, x, tab, Wu, w16 + WU16);
    layernorm_kernel<<<NROWS / 8, 256>>>(x, n1w, n1b, xn16);
    conv16<<<2048, 256>>>(emb, w16 + EMB16, VOCAB * DMODEL / 4);
    gemm_f16<3><<<dim3(3 * TDIM / 128, NROWS / 128), 256, GEMM_SMEM>>>(
        xn16, w16 + WU16, nullptr, nullptr, nullptr, u16, tab, 3 * TDIM, DMODEL);

    // fork: Wo/F1/F2 conversions overlap attention of layer 0
    cudaEventRecord(evF, 0);
    cudaStreamWaitEvent(s2, evF, 0);
    conv16<<<2048, 256, 0, s2>>>(Wo,  w16 + WO16,  NLAYER * DMODEL * TDIM / 4);
    conv16<<<2048, 256, 0, s2>>>(f1w, w16 + F116,  NLAYER * FFDIM * DMODEL / 4);
    conv16<<<2048, 256, 0, s2>>>(f2w, w16 + F216,  NLAYER * DMODEL * FFDIM / 4);
    cudaEventRecord(evD, s2);

    attn_mma<<<dim3(SEQ / 128, NHEAD, BATCH), 256, ATTN_SMEM>>>(u16, at16);
    cudaStreamWaitEvent(0, evD, 0);

    for (int l = 0; l < NLAYER; l++) {
        const __half* Wu_l = w16 + WU16 + (size_t)l * 3 * TDIM * DMODEL;
        const __half* Wo_l = w16 + WO16 + (size_t)l * DMODEL * TDIM;
        const __half* f1_l = w16 + F116 + (size_t)l * FFDIM * DMODEL;
        const __half* f2_l = w16 + F216 + (size_t)l * DMODEL * FFDIM;

        if (l > 0) {
            layernorm_kernel<<<NROWS / 8, 256>>>(x, n1w + l * DMODEL, n1b + l * DMODEL, xn16);
            gemm_f16<3><<<dim3(3 * TDIM / 128, NROWS / 128), 256, GEMM_SMEM>>>(
                xn16, Wu_l, nullptr, nullptr, nullptr, u16, tab, 3 * TDIM, DMODEL);
            attn_mma<<<dim3(SEQ / 128, NHEAD, BATCH), 256, ATTN_SMEM>>>(u16, at16);
        }

        gemm_f16<2><<<dim3(DMODEL / 128, NROWS / 128), 256, GEMM_SMEM>>>(
            at16, Wo_l, nullptr, x, x, nullptr, nullptr, DMODEL, TDIM);

        layernorm_kernel<<<NROWS / 8, 256>>>(x, n2w + l * DMODEL, n2b + l * DMODEL, xn16);

        gemm_f16<1><<<dim3(FFDIM / 128, NROWS / 128), 256, GEMM_SMEM>>>(
            xn16, f1_l, f1b + (size_t)l * FFDIM, nullptr, nullptr, h16, nullptr, FFDIM, DMODEL);

        gemm_f16<2><<<dim3(DMODEL / 128, NROWS / 128), 256, GEMM_SMEM>>>(
            h16, f2_l, f2b + (size_t)l * DMODEL, x, x, nullptr, nullptr, DMODEL, FFDIM);
    }

    layernorm_kernel<<<NROWS / 8, 256>>>(x, fnw, fnb, xn16);

    gemm_f16<0><<<dim3(VOCAB / 128, NROWS / 128), 256, GEMM_SMEM>>>(
        xn16, w16 + EMB16, nullptr, nullptr, out, nullptr, nullptr, VOCAB, DMODEL);
}